// round 10
// baseline (speedup 1.0000x reference)
#include <cuda_runtime.h>
#include <cuda_bf16.h>
#include <cstdint>
#include <math.h>

#define NB   8
#define EE   256
#define LL   64
#define SS   4096
#define QKV  768

// ---------------- scratch ----------------
__device__ float g_Y[NB * QKV * SS];      // [n][e][s]; raw-reshape view [n][s][768]
__device__ float g_qland[NB * LL * EE];
__device__ float g_kland[NB * LL * EE];
__device__ float g_S1[NB * SS * LL];
__device__ float g_pmax[NB * 8 * LL];
__device__ float g_psum[NB * 8 * LL];
__device__ float g_m[NB * LL];
__device__ float g_sinv[NB * LL];
__device__ float g_S3[NB * LL * SS];
__device__ float g_T3p[NB * 16 * LL * EE];
__device__ float g_T3[NB * LL * EE];
__device__ float g_O[NB * SS * EE];       // [n][i][e]; raw view [n][256][4096]

// split-bf16 operands
__device__ __nv_bfloat16 g_wqh[QKV * 256], g_wql[QKV * 256];
__device__ __nv_bfloat16 g_woh[256 * 256], g_wol[256 * 256];
__device__ __nv_bfloat16 g_xh[NB * SS * 256], g_xl[NB * SS * 256];     // [n][s][k]
__device__ __nv_bfloat16 g_oh[NB * SS * 256], g_ol[NB * SS * 256];     // [n][s][k]
__device__ __nv_bfloat16 g_qbh[NB * SS * 256], g_qbl[NB * SS * 256];   // q [n][s][e] (flat view)
__device__ __nv_bfloat16 g_kbh[NB * SS * 256], g_kbl[NB * SS * 256];   // k [n][s][e] (flat view)
__device__ __nv_bfloat16 g_vth[NB * 256 * SS], g_vtl[NB * 256 * SS];   // vT [n][e][s]
__device__ __nv_bfloat16 g_qlbh[NB * LL * 256], g_qlbl[NB * LL * 256];
__device__ __nv_bfloat16 g_klbh[NB * LL * 256], g_klbl[NB * LL * 256];
__device__ __nv_bfloat16 g_M2h[NB * 256 * LL], g_M2l[NB * 256 * LL];   // M2sT [n][e][j]

__device__ __forceinline__ uint32_t smem_u32(const void* p) {
    uint32_t a;
    asm("{ .reg .u64 t; cvta.to.shared.u64 t, %1; cvt.u32.u64 %0, t; }" : "=r"(a) : "l"(p));
    return a;
}
__device__ __forceinline__ void mma_bf16(float* d, uint32_t a0, uint32_t a1, uint32_t a2,
                                         uint32_t a3, uint32_t b0, uint32_t b1) {
    asm volatile(
        "mma.sync.aligned.m16n8k16.row.col.f32.bf16.bf16.f32 "
        "{%0,%1,%2,%3}, {%4,%5,%6,%7}, {%8,%9}, {%0,%1,%2,%3};"
        : "+f"(d[0]), "+f"(d[1]), "+f"(d[2]), "+f"(d[3])
        : "r"(a0), "r"(a1), "r"(a2), "r"(a3), "r"(b0), "r"(b1));
}
__device__ __forceinline__ uint32_t pack2(float a, float b) {
    __nv_bfloat162 h = __floats2bfloat162_rn(a, b);
    return *(uint32_t*)&h;
}
#define CPA16(d, s) asm volatile("cp.async.cg.shared.global [%0], [%1], 16;" :: "r"(d), "l"(s))
#define CPA_COMMIT() asm volatile("cp.async.commit_group;" ::: "memory")
#define CPA_WAIT0()  asm volatile("cp.async.wait_group 0;" ::: "memory")
#define CPA_WAIT1()  asm volatile("cp.async.wait_group 1;" ::: "memory")

// ================= big split-bf16 GEMM (verified R5) =================
#define MG_STAGE 40960
#define MG_SMEM  (2 * MG_STAGE)
__global__ __launch_bounds__(256, 2) void mma_gemm_k(
    const __nv_bfloat16* __restrict__ Ah, const __nv_bfloat16* __restrict__ Al,
    const __nv_bfloat16* __restrict__ Bh, const __nv_bfloat16* __restrict__ Bl,
    float* __restrict__ C, const float* __restrict__ bias,
    long bStride, long cStride)
{
    extern __shared__ char smc[];
    const int tid = threadIdx.x;
    const int lane = tid & 31, wid = tid >> 5;
    const int wm = wid >> 2, ws = wid & 3;
    const int gid = lane >> 2, tg = lane & 3;
    const int n = blockIdx.z;
    const int m0 = blockIdx.y * 128, s0 = blockIdx.x * 128;

    const __nv_bfloat16* gsrc[4];
    gsrc[0] = Ah + (long)m0 * 256;
    gsrc[1] = Al + (long)m0 * 256;
    gsrc[2] = Bh + (long)n * bStride + (long)s0 * 256;
    gsrc[3] = Bl + (long)n * bStride + (long)s0 * 256;

    float acc[4][4][4];
#pragma unroll
    for (int a = 0; a < 4; a++)
#pragma unroll
        for (int b = 0; b < 4; b++)
#pragma unroll
            for (int c = 0; c < 4; c++) acc[a][b][c] = 0.f;

    auto issue = [&](int c, int buf) {
#pragma unroll
        for (int it = 0; it < 8; it++) {
            int idx = tid + it * 256;
            int mat = idx >> 9, rr = (idx >> 2) & 127, seg = idx & 3;
            uint32_t d = smem_u32(smc + buf * MG_STAGE + mat * 10240 + rr * 80 + seg * 16);
            const __nv_bfloat16* s = gsrc[mat] + rr * 256 + c * 32 + seg * 8;
            CPA16(d, s);
        }
        CPA_COMMIT();
    };

    issue(0, 0);
    for (int c = 0; c < 8; c++) {
        if (c < 7) { issue(c + 1, (c + 1) & 1); CPA_WAIT1(); }
        else CPA_WAIT0();
        __syncthreads();
        const char* st = smc + (c & 1) * MG_STAGE;
#pragma unroll
        for (int ks = 0; ks < 2; ks++) {
            uint32_t bh[4][2], bl[4][2];
#pragma unroll
            for (int nt = 0; nt < 4; nt++) {
                int nrow = ws * 32 + nt * 8 + gid;
                const char* pb = st + 20480 + nrow * 80 + (ks * 16 + tg * 2) * 2;
                bh[nt][0] = *(const uint32_t*)pb;
                bh[nt][1] = *(const uint32_t*)(pb + 16);
                bl[nt][0] = *(const uint32_t*)(pb + 10240);
                bl[nt][1] = *(const uint32_t*)(pb + 10256);
            }
#pragma unroll
            for (int mt = 0; mt < 4; mt++) {
                int arow = wm * 64 + mt * 16 + gid;
                const char* pa = st + arow * 80 + (ks * 16 + tg * 2) * 2;
                uint32_t ah0 = *(const uint32_t*)pa;
                uint32_t ah1 = *(const uint32_t*)(pa + 640);
                uint32_t ah2 = *(const uint32_t*)(pa + 16);
                uint32_t ah3 = *(const uint32_t*)(pa + 656);
                uint32_t al0 = *(const uint32_t*)(pa + 10240);
                uint32_t al1 = *(const uint32_t*)(pa + 10880);
                uint32_t al2 = *(const uint32_t*)(pa + 10256);
                uint32_t al3 = *(const uint32_t*)(pa + 10896);
#pragma unroll
                for (int nt = 0; nt < 4; nt++) {
                    mma_bf16(acc[mt][nt], ah0, ah1, ah2, ah3, bh[nt][0], bh[nt][1]);
                    mma_bf16(acc[mt][nt], ah0, ah1, ah2, ah3, bl[nt][0], bl[nt][1]);
                    mma_bf16(acc[mt][nt], al0, al1, al2, al3, bh[nt][0], bh[nt][1]);
                }
            }
        }
        __syncthreads();
    }

    float* Cn = C + (long)n * cStride;
#pragma unroll
    for (int mt = 0; mt < 4; mt++) {
        int r0 = m0 + wm * 64 + mt * 16 + gid;
        float b0v = bias[r0], b1v = bias[r0 + 8];
#pragma unroll
        for (int nt = 0; nt < 4; nt++) {
            int col = s0 + ws * 32 + nt * 8 + tg * 2;
            *(float2*)(Cn + (long)r0 * 4096 + col) =
                make_float2(acc[mt][nt][0] + b0v, acc[mt][nt][1] + b0v);
            *(float2*)(Cn + (long)(r0 + 8) * 4096 + col) =
                make_float2(acc[mt][nt][2] + b1v, acc[mt][nt][3] + b1v);
        }
    }
}

// ================= converts =================
__global__ void cvt_w_k(const float* __restrict__ src, __nv_bfloat16* __restrict__ hi,
                        __nv_bfloat16* __restrict__ lo, int nElem)
{
    int i = blockIdx.x * 256 + threadIdx.x;
    if (i < nElem) {
        float v = src[i];
        __nv_bfloat16 h = __float2bfloat16(v);
        hi[i] = h;
        lo[i] = __float2bfloat16(v - __bfloat162float(h));
    }
}

// transpose convert: src [256][4096] -> dst [4096][256] hi/lo  (used for x and O)
__global__ void tcvt_k(const float* __restrict__ src, __nv_bfloat16* __restrict__ hi,
                       __nv_bfloat16* __restrict__ lo, long srcBatchStride)
{
    __shared__ float t[32][33];
    int n = blockIdx.z;
    const float* S = src + (long)n * srcBatchStride;
    int s0 = blockIdx.x * 32, k0 = blockIdx.y * 32;
    int tx = threadIdx.x, ty = threadIdx.y;
#pragma unroll
    for (int i = 0; i < 32; i += 8) t[ty + i][tx] = S[(long)(k0 + ty + i) * 4096 + s0 + tx];
    __syncthreads();
    long base = (long)n * 1048576;
#pragma unroll
    for (int i = 0; i < 32; i += 8) {
        float v = t[tx][ty + i];
        __nv_bfloat16 h = __float2bfloat16(v);
        long o = base + (long)(s0 + ty + i) * 256 + k0 + tx;
        hi[o] = h;
        lo[o] = __float2bfloat16(v - __bfloat162float(h));
    }
}

// q/k straight converts from the raw-reshape flat view:
// qb[n][s][e] = Yflat[n][s*768 + e],  kb[n][s][e] = Yflat[n][s*768 + 256 + e]
__global__ void qkcvt_k()
{
    long i4 = ((long)blockIdx.x * 256 + threadIdx.x) * 4;   // over NB*SS*256 elems
    int n = (int)(i4 >> 20);
    long rem = i4 & 1048575;
    long s = rem >> 8;
    int e = (int)(rem & 255);
    const float* src = g_Y + (long)n * 3145728 + s * 768 + e;
    float4 q4 = *(const float4*)src;
    float4 k4 = *(const float4*)(src + 256);
    long o = (long)n * 1048576 + rem;
    float qv[4] = {q4.x, q4.y, q4.z, q4.w};
    float kv[4] = {k4.x, k4.y, k4.z, k4.w};
#pragma unroll
    for (int p = 0; p < 4; p++) {
        __nv_bfloat16 qh = __float2bfloat16(qv[p]);
        __nv_bfloat16 kh = __float2bfloat16(kv[p]);
        g_qbh[o + p] = qh; g_qbl[o + p] = __float2bfloat16(qv[p] - __bfloat162float(qh));
        g_kbh[o + p] = kh; g_kbl[o + p] = __float2bfloat16(kv[p] - __bfloat162float(kh));
    }
}

// vT transpose convert: vT[n][e][s] = Yflat[n][s*768 + 512 + e]
__global__ void vtcvt_k()
{
    __shared__ float t[32][33];
    int n = blockIdx.z;
    int s0 = blockIdx.x * 32, e0 = blockIdx.y * 32;
    int tx = threadIdx.x, ty = threadIdx.y;
    const float* S = g_Y + (long)n * 3145728;
#pragma unroll
    for (int i = 0; i < 32; i += 8)
        t[ty + i][tx] = S[(long)(s0 + ty + i) * 768 + 512 + e0 + tx];
    __syncthreads();
    long base = (long)n * 1048576;
#pragma unroll
    for (int i = 0; i < 32; i += 8) {
        float v = t[tx][ty + i];
        __nv_bfloat16 h = __float2bfloat16(v);
        long o = base + (long)(e0 + ty + i) * 4096 + s0 + tx;
        g_vth[o] = h;
        g_vtl[o] = __float2bfloat16(v - __bfloat162float(h));
    }
}

__global__ void cvt_land_k()
{
    int i = blockIdx.x * 256 + threadIdx.x;   // < 131072
    float a = g_qland[i], b = g_kland[i];
    __nv_bfloat16 ha = __float2bfloat16(a), hb = __float2bfloat16(b);
    g_qlbh[i] = ha; g_qlbl[i] = __float2bfloat16(a - __bfloat162float(ha));
    g_klbh[i] = hb; g_klbl[i] = __float2bfloat16(b - __bfloat162float(hb));
}

// ================= landmarks (flat view, verified) =================
__global__ void landmarks_k()
{
    int n = blockIdx.x, l = blockIdx.y, e = threadIdx.x;
    const float* base = g_Y + (long)n * QKV * SS;
    float aq = 0.f, ak = 0.f;
#pragma unroll 4
    for (int r = 0; r < 64; r++) {
        long off = (long)(l * 64 + r) * QKV;
        aq += base[off + e];
        ak += base[off + 256 + e];
    }
    g_qland[(n * LL + l) * EE + e] = aq * (1.f / 4096.f);
    g_kland[(n * LL + l) * EE + e] = ak * (1.f / 4096.f);
}

// ================= S1 = q @ kland^T  (mma, 128m x 64n, K=256) =================
#define S1_STAGE 30720
__global__ __launch_bounds__(256, 2) void s1_mma_k()
{
    extern __shared__ char smc[];
    int tid = threadIdx.x, lane = tid & 31, wid = tid >> 5;
    int wm = wid >> 1, ws = wid & 1, gid = lane >> 2, tg = lane & 3;
    int n = blockIdx.y, i0 = blockIdx.x * 128;
    const __nv_bfloat16* Ah = g_qbh + (long)n * 1048576 + (long)i0 * 256;
    const __nv_bfloat16* Al = g_qbl + (long)n * 1048576 + (long)i0 * 256;
    const __nv_bfloat16* Bh = g_klbh + n * 16384;
    const __nv_bfloat16* Bl = g_klbl + n * 16384;

    float acc[2][4][4];
#pragma unroll
    for (int a = 0; a < 2; a++)
#pragma unroll
        for (int b = 0; b < 4; b++)
#pragma unroll
            for (int c = 0; c < 4; c++) acc[a][b][c] = 0.f;

    auto issue = [&](int c, int buf) {
#pragma unroll
        for (int it = 0; it < 6; it++) {
            int idx = tid + it * 256;
            uint32_t d; const __nv_bfloat16* s;
            if (idx < 1024) {
                int half = idx >> 9, r = (idx >> 2) & 127, seg = idx & 3;
                d = smem_u32(smc + buf * S1_STAGE + half * 10240 + r * 80 + seg * 16);
                s = (half ? Al : Ah) + r * 256 + c * 32 + seg * 8;
            } else {
                int j = idx - 1024;
                int half = j >> 8, r = (j >> 2) & 63, seg = j & 3;
                d = smem_u32(smc + buf * S1_STAGE + 20480 + half * 5120 + r * 80 + seg * 16);
                s = (half ? Bl : Bh) + r * 256 + c * 32 + seg * 8;
            }
            CPA16(d, s);
        }
        CPA_COMMIT();
    };

    issue(0, 0);
    for (int c = 0; c < 8; c++) {
        if (c < 7) { issue(c + 1, (c + 1) & 1); CPA_WAIT1(); }
        else CPA_WAIT0();
        __syncthreads();
        const char* st = smc + (c & 1) * S1_STAGE;
#pragma unroll
        for (int ks = 0; ks < 2; ks++) {
            uint32_t bh[4][2], bl[4][2];
#pragma unroll
            for (int nt = 0; nt < 4; nt++) {
                int nrow = ws * 32 + nt * 8 + gid;
                const char* pb = st + 20480 + nrow * 80 + (ks * 16 + tg * 2) * 2;
                bh[nt][0] = *(const uint32_t*)pb;
                bh[nt][1] = *(const uint32_t*)(pb + 16);
                bl[nt][0] = *(const uint32_t*)(pb + 5120);
                bl[nt][1] = *(const uint32_t*)(pb + 5136);
            }
#pragma unroll
            for (int mt = 0; mt < 2; mt++) {
                int arow = wm * 32 + mt * 16 + gid;
                const char* pa = st + arow * 80 + (ks * 16 + tg * 2) * 2;
                uint32_t ah0 = *(const uint32_t*)pa;
                uint32_t ah1 = *(const uint32_t*)(pa + 640);
                uint32_t ah2 = *(const uint32_t*)(pa + 16);
                uint32_t ah3 = *(const uint32_t*)(pa + 656);
                uint32_t al0 = *(const uint32_t*)(pa + 10240);
                uint32_t al1 = *(const uint32_t*)(pa + 10880);
                uint32_t al2 = *(const uint32_t*)(pa + 10256);
                uint32_t al3 = *(const uint32_t*)(pa + 10896);
#pragma unroll
                for (int nt = 0; nt < 4; nt++) {
                    mma_bf16(acc[mt][nt], ah0, ah1, ah2, ah3, bh[nt][0], bh[nt][1]);
                    mma_bf16(acc[mt][nt], ah0, ah1, ah2, ah3, bl[nt][0], bl[nt][1]);
                    mma_bf16(acc[mt][nt], al0, al1, al2, al3, bh[nt][0], bh[nt][1]);
                }
            }
        }
        __syncthreads();
    }
#pragma unroll
    for (int mt = 0; mt < 2; mt++) {
        int r0 = i0 + wm * 32 + mt * 16 + gid;
#pragma unroll
        for (int nt = 0; nt < 4; nt++) {
            int col = ws * 32 + nt * 8 + tg * 2;
            float* dst = g_S1 + ((long)n * 4096 + r0) * 64 + col;
            *(float2*)dst = make_float2(acc[mt][nt][0], acc[mt][nt][1]);
            *(float2*)(dst + 512) = make_float2(acc[mt][nt][2], acc[mt][nt][3]);
        }
    }
}

// ================= S3 = qland @ k^T (mma, 64m x 128n, K=256) =================
__global__ __launch_bounds__(256, 2) void s3_mma_k()
{
    extern __shared__ char smc[];
    int tid = threadIdx.x, lane = tid & 31, wid = tid >> 5;
    int wm = wid >> 2, ws = wid & 3, gid = lane >> 2, tg = lane & 3;
    int n = blockIdx.y, s0 = blockIdx.x * 128;
    const __nv_bfloat16* Ah = g_qlbh + n * 16384;
    const __nv_bfloat16* Al = g_qlbl + n * 16384;
    const __nv_bfloat16* Bh = g_kbh + (long)n * 1048576 + (long)s0 * 256;
    const __nv_bfloat16* Bl = g_kbl + (long)n * 1048576 + (long)s0 * 256;

    float acc[2][4][4];
#pragma unroll
    for (int a = 0; a < 2; a++)
#pragma unroll
        for (int b = 0; b < 4; b++)
#pragma unroll
            for (int c = 0; c < 4; c++) acc[a][b][c] = 0.f;

    auto issue = [&](int c, int buf) {
#pragma unroll
        for (int it = 0; it < 6; it++) {
            int idx = tid + it * 256;
            uint32_t d; const __nv_bfloat16* s;
            if (idx < 512) {
                int half = idx >> 8, r = (idx >> 2) & 63, seg = idx & 3;
                d = smem_u32(smc + buf * S1_STAGE + half * 5120 + r * 80 + seg * 16);
                s = (half ? Al : Ah) + r * 256 + c * 32 + seg * 8;
            } else {
                int j = idx - 512;
                int half = j >> 9, r = (j >> 2) & 127, seg = j & 3;
                d = smem_u32(smc + buf * S1_STAGE + 10240 + half * 10240 + r * 80 + seg * 16);
                s = (half ? Bl : Bh) + r * 256 + c * 32 + seg * 8;
            }
            CPA16(d, s);
        }
        CPA_COMMIT();
    };

    issue(0, 0);
    for (int c = 0; c < 8; c++) {
        if (c < 7) { issue(c + 1, (c + 1) & 1); CPA_WAIT1(); }
        else CPA_WAIT0();
        __syncthreads();
        const char* st = smc + (c & 1) * S1_STAGE;
#pragma unroll
        for (int ks = 0; ks < 2; ks++) {
            uint32_t bh[4][2], bl[4][2];
#pragma unroll
            for (int nt = 0; nt < 4; nt++) {
                int nrow = ws * 32 + nt * 8 + gid;
                const char* pb = st + 10240 + nrow * 80 + (ks * 16 + tg * 2) * 2;
                bh[nt][0] = *(const uint32_t*)pb;
                bh[nt][1] = *(const uint32_t*)(pb + 16);
                bl[nt][0] = *(const uint32_t*)(pb + 10240);
                bl[nt][1] = *(const uint32_t*)(pb + 10256);
            }
#pragma unroll
            for (int mt = 0; mt < 2; mt++) {
                int arow = wm * 32 + mt * 16 + gid;
                const char* pa = st + arow * 80 + (ks * 16 + tg * 2) * 2;
                uint32_t ah0 = *(const uint32_t*)pa;
                uint32_t ah1 = *(const uint32_t*)(pa + 640);
                uint32_t ah2 = *(const uint32_t*)(pa + 16);
                uint32_t ah3 = *(const uint32_t*)(pa + 656);
                uint32_t al0 = *(const uint32_t*)(pa + 5120);
                uint32_t al1 = *(const uint32_t*)(pa + 5760);
                uint32_t al2 = *(const uint32_t*)(pa + 5136);
                uint32_t al3 = *(const uint32_t*)(pa + 5776);
#pragma unroll
                for (int nt = 0; nt < 4; nt++) {
                    mma_bf16(acc[mt][nt], ah0, ah1, ah2, ah3, bh[nt][0], bh[nt][1]);
                    mma_bf16(acc[mt][nt], ah0, ah1, ah2, ah3, bl[nt][0], bl[nt][1]);
                    mma_bf16(acc[mt][nt], al0, al1, al2, al3, bh[nt][0], bh[nt][1]);
                }
            }
        }
        __syncthreads();
    }
#pragma unroll
    for (int mt = 0; mt < 2; mt++) {
        int r0 = wm * 32 + mt * 16 + gid;
#pragma unroll
        for (int nt = 0; nt < 4; nt++) {
            int col = s0 + ws * 32 + nt * 8 + tg * 2;
            float* dst = g_S3 + (long)n * 262144 + (long)r0 * 4096 + col;
            *(float2*)dst = make_float2(acc[mt][nt][0], acc[mt][nt][1]);
            *(float2*)(dst + 8 * 4096) = make_float2(acc[mt][nt][2], acc[mt][nt][3]);
        }
    }
}

// ================= column softmax stats for S1 =================
__global__ void colstats_part_k()
{
    __shared__ float sm2[4][64];
    int stripe = blockIdx.x, n = blockIdx.y;
    int tid = threadIdx.x;
    int j = tid & 63, g = tid >> 6;
    const float* S = g_S1 + (long)n * SS * 64;
    float m = -1e30f;
    for (int i = stripe * 512 + g; i < stripe * 512 + 512; i += 4)
        m = fmaxf(m, S[(long)i * 64 + j]);
    sm2[g][j] = m;
    __syncthreads();
    float mm = fmaxf(fmaxf(sm2[0][j], sm2[1][j]), fmaxf(sm2[2][j], sm2[3][j]));
    float s = 0.f;
    for (int i = stripe * 512 + g; i < stripe * 512 + 512; i += 4)
        s += expf(S[(long)i * 64 + j] - mm);
    __syncthreads();
    sm2[g][j] = s;
    __syncthreads();
    if (g == 0) {
        float ss = sm2[0][j] + sm2[1][j] + sm2[2][j] + sm2[3][j];
        g_pmax[(n * 8 + stripe) * 64 + j] = mm;
        g_psum[(n * 8 + stripe) * 64 + j] = ss;
    }
}

__global__ void colstats_comb_k()
{
    int n = blockIdx.x, j = threadIdx.x;
    float m = -1e30f;
#pragma unroll
    for (int c = 0; c < 8; c++) m = fmaxf(m, g_pmax[(n * 8 + c) * 64 + j]);
    float s = 0.f;
#pragma unroll
    for (int c = 0; c < 8; c++)
        s += g_psum[(n * 8 + c) * 64 + j] * expf(g_pmax[(n * 8 + c) * 64 + j] - m);
    g_m[n * 64 + j] = m;
    g_sinv[n * 64 + j] = 1.f / s;
}

__global__ void softmax_s3_k()
{
    int n = blockIdx.y;
    int s = blockIdx.x * 256 + threadIdx.x;
    float* S = g_S3 + (long)n * LL * SS;
    float v[64];
    float m = -1e30f;
#pragma unroll
    for (int j = 0; j < 64; j++) { v[j] = S[(long)j * SS + s]; m = fmaxf(m, v[j]); }
    float sum = 0.f;
#pragma unroll
    for (int j = 0; j < 64; j++) { v[j] = expf(v[j] - m); sum += v[j]; }
    float r = 1.f / sum;
#pragma unroll
    for (int j = 0; j < 64; j++) S[(long)j * SS + s] = v[j] * r;
}

// ================= T3 = k3 @ v  (mma split-K, 64m x 256n) =================
#define T3_SMEM 51200
__global__ __launch_bounds__(256, 2) void t3_mma_k()
{
    extern __shared__ char smc[];
    int tid = threadIdx.x, lane = tid & 31, wid = tid >> 5;
    int wm = wid >> 2, ws = wid & 3, gid = lane >> 2, tg = lane & 3;
    int n = blockIdx.y, s0 = blockIdx.x * 256;

    float acc[2][8][4];
#pragma unroll
    for (int a = 0; a < 2; a++)
#pragma unroll
        for (int b = 0; b < 8; b++)
#pragma unroll
            for (int c = 0; c < 4; c++) acc[a][b][c] = 0.f;

    for (int cc = 0; cc < 8; cc++) {
        {
            int j = tid >> 2, kq = (tid & 3) * 8;
            const float* s = g_S3 + (long)n * 262144 + (long)j * 4096 + s0 + cc * 32 + kq;
            float4 f0 = *(const float4*)s, f1 = *(const float4*)(s + 4);
            float v[8] = {f0.x, f0.y, f0.z, f0.w, f1.x, f1.y, f1.z, f1.w};
            uint32_t hi[4], lo[4];
#pragma unroll
            for (int p = 0; p < 4; p++) {
                __nv_bfloat16 h0 = __float2bfloat16(v[2 * p]);
                __nv_bfloat16 h1 = __float2bfloat16(v[2 * p + 1]);
                hi[p] = pack2(__bfloat162float(h0), __bfloat162float(h1));
                lo[p] = pack2(v[2 * p] - __bfloat162float(h0), v[2 * p + 1] - __bfloat162float(h1));
            }
            *(uint4*)(smc + 40960 + j * 80 + (kq >> 3) * 16) = *(uint4*)hi;
            *(uint4*)(smc + 46080 + j * 80 + (kq >> 3) * 16) = *(uint4*)lo;
        }
#pragma unroll
        for (int it = 0; it < 8; it++) {
            int idx = tid + it * 256;
            int half = idx >> 10, r = (idx >> 2) & 255, seg = idx & 3;
            uint32_t d = smem_u32(smc + half * 20480 + r * 80 + seg * 16);
            const __nv_bfloat16* s = (half ? g_vtl : g_vth) +
                (long)n * 1048576 + (long)r * 4096 + s0 + cc * 32 + seg * 8;
            CPA16(d, s);
        }
        CPA_COMMIT();
        CPA_WAIT0();
        __syncthreads();
#pragma unroll
        for (int ks = 0; ks < 2; ks++) {
            uint32_t bh[8][2], bl[8][2];
#pragma unroll
            for (int nt = 0; nt < 8; nt++) {
                int nrow = ws * 64 + nt * 8 + gid;
                const char* pb = smc + nrow * 80 + (ks * 16 + tg * 2) * 2;
                bh[nt][0] = *(const uint32_t*)pb;
                bh[nt][1] = *(const uint32_t*)(pb + 16);
                bl[nt][0] = *(const uint32_t*)(pb + 20480);
                bl[nt][1] = *(const uint32_t*)(pb + 20496);
            }
#pragma unroll
            for (int mt = 0; mt < 2; mt++) {
                int arow = wm * 32 + mt * 16 + gid;
                const char* pa = smc + 40960 + arow * 80 + (ks * 16 + tg * 2) * 2;
                uint32_t ah0 = *(const uint32_t*)pa;
                uint32_t ah1 = *(const uint32_t*)(pa + 640);
                uint32_t ah2 = *(const uint32_t*)(pa + 16);
                uint32_t ah3 = *(const uint32_t*)(pa + 656);
                uint32_t al0 = *(const uint32_t*)(pa + 5120);
                uint32_t al1 = *(const uint32_t*)(pa + 5760);
                uint32_t al2 = *(const uint32_t*)(pa + 5136);
                uint32_t al3 = *(const uint32_t*)(pa + 5776);
#pragma unroll
                for (int nt = 0; nt < 8; nt++) {
                    mma_bf16(acc[mt][nt], ah0, ah1, ah2, ah3, bh[nt][0], bh[nt][1]);
                    mma_bf16(acc[mt][nt], ah0, ah1, ah2, ah3, bl[nt][0], bl[nt][1]);
                    mma_bf16(acc[mt][nt], al0, al1, al2, al3, bh[nt][0], bh[nt][1]);
                }
            }
        }
        __syncthreads();
    }
    float* dst = g_T3p + (long)(n * 16 + blockIdx.x) * 16384;
#pragma unroll
    for (int mt = 0; mt < 2; mt++) {
        int r0 = wm * 32 + mt * 16 + gid;
#pragma unroll
        for (int nt = 0; nt < 8; nt++) {
            int col = ws * 64 + nt * 8 + tg * 2;
            *(float2*)(dst + r0 * 256 + col) = make_float2(acc[mt][nt][0], acc[mt][nt][1]);
            *(float2*)(dst + (r0 + 8) * 256 + col) = make_float2(acc[mt][nt][2], acc[mt][nt][3]);
        }
    }
}

__global__ void t3_reduce_k()
{
    int idx = blockIdx.x * 256 + threadIdx.x;
    int n = idx >> 14;
    int r = idx & 16383;
    const float* p = g_T3p + (long)n * 16 * 16384 + r;
    float s = 0.f;
#pragma unroll
    for (int c = 0; c < 16; c++) s += p[(long)c * 16384];
    g_T3[idx] = s;
}

// ================= 64x64 smem matmul + k2inv (NS) =================
__device__ __forceinline__ void mm64(float* D, const float* A, const float* B, int tid)
{
    int r = (tid >> 5) * 2;
    int c = (tid & 31) * 2;
    float d00 = 0.f, d01 = 0.f, d10 = 0.f, d11 = 0.f;
#pragma unroll 16
    for (int k = 0; k < 64; k++) {
        float a0 = A[r * 64 + k], a1 = A[(r + 1) * 64 + k];
        float b0 = B[k * 64 + c], b1 = B[k * 64 + c + 1];
        d00 += a0 * b0; d01 += a0 * b1; d10 += a1 * b0; d11 += a1 * b1;
    }
    D[r * 64 + c] = d00; D[r * 64 + c + 1] = d01;
    D[(r + 1) * 64 + c] = d10; D[(r + 1) * 64 + c + 1] = d11;
    __syncthreads();
}

#define K2INV_SMEM_FLOATS (4096 * 5 + 2048 * 2 + 192)
__global__ __launch_bounds__(1024) void k2inv_k()
{
    extern __shared__ float sm[];
    float* K2 = sm;
    float* Vv = sm + 4096;
    float* BA = sm + 8192;
    float* BB = sm + 12288;
    float* BC = sm + 16384;
    float* QL = sm + 20480;
    float* KT = sm + 22528;
    float* red = sm + 24576;

    int n = blockIdx.x;
    int tid = threadIdx.x;
    const float* ql = g_qland + n * 16384;
    const float* kl = g_kland + n * 16384;

    float accS[4] = {0.f, 0.f, 0.f, 0.f};
    for (int e0 = 0; e0 < 256; e0 += 32) {
#pragma unroll
        for (int p = 0; p < 2; p++) {
            int t = tid + p * 1024;
            int r = t >> 5, c = t & 31;
            QL[r * 32 + c] = ql[r * 256 + e0 + c];
            KT[c * 64 + r] = kl[r * 256 + e0 + c];
        }
        __syncthreads();
#pragma unroll
        for (int p = 0; p < 4; p++) {
            int t = tid + p * 1024;
            int i = t >> 6, j = t & 63;
            float a = 0.f;
#pragma unroll
            for (int ec = 0; ec < 32; ec++) a += QL[i * 32 + ec] * KT[ec * 64 + j];
            accS[p] += a;
        }
        __syncthreads();
    }
#pragma unroll
    for (int p = 0; p < 4; p++) K2[tid + p * 1024] = accS[p];
    __syncthreads();

    if (tid < 64) {
        int j = tid;
        float m = -1e30f;
        for (int i = 0; i < 64; i++) m = fmaxf(m, K2[i * 64 + j]);
        float s = 0.f;
        for (int i = 0; i < 64; i++) s += expf(K2[i * 64 + j] - m);
        red[j] = m; red[64 + j] = 1.f / s;
    }
    __syncthreads();
#pragma unroll
    for (int p = 0; p < 4; p++) {
        int t = tid + p * 1024;
        int j = t & 63;
        K2[t] = expf(K2[t] - red[j]) * red[64 + j];
    }
    __syncthreads();

    if (tid < 64) {
        int i = tid;
        float rs = 0.f, cs = 0.f;
        for (int j = 0; j < 64; j++) { rs += fabsf(K2[i * 64 + j]); cs += fabsf(K2[j * 64 + i]); }
        red[i] = rs; red[64 + i] = cs;
    }
    __syncthreads();
    if (tid == 0) {
        float vi = 0.f, v0 = 0.f;
        for (int t = 0; t < 64; t++) { vi = fmaxf(vi, red[t]); v0 = fmaxf(v0, red[64 + t]); }
        red[128] = 1.f / (v0 * vi);
    }
    __syncthreads();
    float isc = red[128];
#pragma unroll
    for (int p = 0; p < 4; p++) {
        int t = tid + p * 1024;
        int a = t >> 6, b = t & 63;
        Vv[t] = K2[b * 64 + a] * isc;
    }
    __syncthreads();

    for (int it = 0; it < 6; it++) {
        mm64(BA, K2, Vv, tid);
        mm64(BB, BA, BA, tid);
#pragma unroll
        for (int p = 0; p < 4; p++) {
            int t = tid + p * 1024;
            float d = ((t >> 6) == (t & 63)) ? 15.f : 0.f;
            BB[t] = d - 7.f * BA[t] + BB[t];
        }
        __syncthreads();
        mm64(BC, BA, BB, tid);
#pragma unroll
        for (int p = 0; p < 4; p++) {
            int t = tid + p * 1024;
            float d = ((t >> 6) == (t & 63)) ? 13.f : 0.f;
            BC[t] = d - BC[t];
        }
        __syncthreads();
        mm64(BB, Vv, BC, tid);
#pragma unroll
        for (int p = 0; p < 4; p++) {
            int t = tid + p * 1024;
            Vv[t] = 0.25f * BB[t];
        }
        __syncthreads();
    }

    // M2sT (bf16 hi/lo) = transpose((Vv @ T3) * sinv_j)
    const float* T3 = g_T3 + n * 16384;
    for (int t = tid; t < 16384; t += 1024) {
        int j = t >> 8, e = t & 255;
        float a = 0.f;
#pragma unroll
        for (int k = 0; k < 64; k++) a += Vv[j * 64 + k] * T3[k * 256 + e];
        a *= g_sinv[n * 64 + j];
        __nv_bfloat16 h = __float2bfloat16(a);
        g_M2h[n * 16384 + e * 64 + j] = h;
        g_M2l[n * 16384 + e * 64 + j] = __float2bfloat16(a - __bfloat162float(h));
    }
}

// ================= out = exp(S1-m) @ M2sT^T + v  (mma, 128m x 256n, K=64) =================
#define OUT_SMEM 61696
__global__ __launch_bounds__(256, 1) void out_mma_k()
{
    extern __shared__ char smc[];
    float* ms = (float*)smc;
    int tid = threadIdx.x, lane = tid & 31, wid = tid >> 5;
    int wm = wid >> 2, ws = wid & 3, gid = lane >> 2, tg = lane & 3;
    int n = blockIdx.y, i0 = blockIdx.x * 128;

    if (tid < 64) ms[tid] = g_m[n * 64 + tid];
    __syncthreads();

    float acc[4][8][4];
#pragma unroll
    for (int a = 0; a < 4; a++)
#pragma unroll
        for (int b = 0; b < 8; b++)
#pragma unroll
            for (int c = 0; c < 4; c++) acc[a][b][c] = 0.f;

    for (int c = 0; c < 2; c++) {
        if (c) __syncthreads();
        {
            int row = tid >> 1, kq = (tid & 1) * 16;
            const float* Sr = g_S1 + ((long)n * 4096 + i0 + row) * 64 + c * 32 + kq;
            float v[16];
            *(float4*)&v[0]  = *(const float4*)Sr;
            *(float4*)&v[4]  = *(const float4*)(Sr + 4);
            *(float4*)&v[8]  = *(const float4*)(Sr + 8);
            *(float4*)&v[12] = *(const float4*)(Sr + 12);
            uint32_t hi[8], lo[8];
#pragma unroll
            for (int p = 0; p < 8; p++) {
                float e0 = expf(v[2 * p] - ms[c * 32 + kq + 2 * p]);
                float e1 = expf(v[2 * p + 1] - ms[c * 32 + kq + 2 * p + 1]);
                __nv_bfloat16 h0 = __float2bfloat16(e0), h1 = __float2bfloat16(e1);
                hi[p] = pack2(__bfloat162float(h0), __bfloat162float(h1));
                lo[p] = pack2(e0 - __bfloat162float(h0), e1 - __bfloat162float(h1));
            }
            char* pa = smc + 256 + row * 80 + (kq >> 3) * 16;
            *(uint4*)pa = *(uint4*)hi;
            *(uint4*)(pa + 16) = *(uint4*)&hi[4];
            char* pl = smc + 10496 + row * 80 + (kq >> 3) * 16;
            *(uint4*)pl = *(uint4*)lo;
            *(uint4*)(pl + 16) = *(uint4*)&lo[4];
        }
#pragma unroll
        for (int it = 0; it < 8; it++) {
            int idx = tid + it * 256;
            int half = idx >> 10, r = (idx >> 2) & 255, seg = idx & 3;
            uint32_t d = smem_u32(smc + 20736 + half * 20480 + r * 80 + seg * 16);
            const __nv_bfloat16* s = (half ? g_M2l : g_M2h) + n * 16384 + r * 64 + c * 32 + seg * 8;
            CPA16(d, s);
        }
        CPA_COMMIT();
        CPA_WAIT0();
        __syncthreads();
#pragma unroll
        for (int ks = 0; ks < 2; ks++) {
            uint32_t bh[8][2], bl[8][2];
#pragma unroll
            for (int nt = 0; nt < 8; nt++) {
                int nrow = ws * 64 + nt * 8 + gid;
                const char* pb = smc + 20736 + nrow * 80 + (ks * 16 + tg * 2) * 2;
                bh[nt][0] = *(const uint32_t*)pb;
                bh[nt][1] = *(const uint32_t*)(pb + 16);
                bl[nt][0] = *(const uint32_t*)(pb + 20480);
                bl[nt][1] = *(const uint32_t*)(pb + 20496);
            }
#pragma unroll
            for (int mt = 0; mt < 4; mt++) {
                int arow = wm * 64 + mt * 16 + gid;
                const char* pa = smc + 256 + arow * 80 + (ks * 16 + tg * 2) * 2;
                uint32_t ah0 = *(const uint32_t*)pa;
                uint32_t ah1 = *(const uint32_t*)(pa + 640);
                uint32_t ah2 = *(const uint32_t*)(pa + 16);
                uint32_t ah3 = *(const uint32_t*)(pa + 656);
                uint32_t al0 = *(const uint32_t*)(pa + 10240);
                uint32_t al1 = *(const uint32_t*)(pa + 10880);
                uint32_t al2 = *(const uint32_t*)(pa + 10256);
                uint32_t al3 = *(const uint32_t*)(pa + 10896);
#pragma unroll
                for (int nt = 0; nt < 8; nt++) {
                    mma_bf16(acc[mt][nt], ah0, ah1, ah2, ah3, bh[nt][0], bh[nt][1]);
                    mma_bf16(acc[mt][nt], ah0, ah1, ah2, ah3, bl[nt][0], bl[nt][1]);
                    mma_bf16(acc[mt][nt], al0, al1, al2, al3, bh[nt][0], bh[nt][1]);
                }
            }
        }
    }

    const float* vb = g_Y + (long)n * QKV * SS + 512;
    float* ob = g_O + (long)n * SS * EE;
#pragma unroll
    for (int mt = 0; mt < 4; mt++) {
        int r0 = i0 + wm * 64 + mt * 16 + gid;
#pragma unroll
        for (int nt = 0; nt < 8; nt++) {
            int col = ws * 64 + nt * 8 + tg * 2;
            float2 v0 = *(const float2*)(vb + (long)r0 * 768 + col);
            float2 v1 = *(const float2*)(vb + (long)(r0 + 8) * 768 + col);
            *(float2*)(ob + (long)r0 * 256 + col) =
                make_float2(acc[mt][nt][0] + v0.x, acc[mt][nt][1] + v0.y);
            *(float2*)(ob + (long)(r0 + 8) * 256 + col) =
                make_float2(acc[mt][nt][2] + v1.x, acc[mt][nt][3] + v1.y);
        }
    }
}

// ---------------- host ----------------
extern "C" void kernel_launch(void* const* d_in, const int* in_sizes, int n_in,
                              void* d_out, int out_size)
{
    const float* x     = (const float*)d_in[0];
    const float* w_qkv = (const float*)d_in[1];
    const float* b_qkv = (const float*)d_in[2];
    const float* w_out = (const float*)d_in[3];
    const float* b_out = (const float*)d_in[4];
    float* out = (float*)d_out;

    cudaFuncSetAttribute(k2inv_k, cudaFuncAttributeMaxDynamicSharedMemorySize,
                         K2INV_SMEM_FLOATS * (int)sizeof(float));
    cudaFuncSetAttribute(mma_gemm_k, cudaFuncAttributeMaxDynamicSharedMemorySize, MG_SMEM);
    cudaFuncSetAttribute(s1_mma_k, cudaFuncAttributeMaxDynamicSharedMemorySize, 2 * S1_STAGE);
    cudaFuncSetAttribute(s3_mma_k, cudaFuncAttributeMaxDynamicSharedMemorySize, 2 * S1_STAGE);
    cudaFuncSetAttribute(t3_mma_k, cudaFuncAttributeMaxDynamicSharedMemorySize, T3_SMEM);
    cudaFuncSetAttribute(out_mma_k, cudaFuncAttributeMaxDynamicSharedMemorySize, OUT_SMEM);

    void *yb, *ob;
    cudaGetSymbolAddress(&yb, g_Y);
    cudaGetSymbolAddress(&ob, g_O);
    void *wqh, *wql, *woh, *wol, *xh, *xl, *oh, *ol;
    cudaGetSymbolAddress(&wqh, g_wqh); cudaGetSymbolAddress(&wql, g_wql);
    cudaGetSymbolAddress(&woh, g_woh); cudaGetSymbolAddress(&wol, g_wol);
    cudaGetSymbolAddress(&xh, g_xh);   cudaGetSymbolAddress(&xl, g_xl);
    cudaGetSymbolAddress(&oh, g_oh);   cudaGetSymbolAddress(&ol, g_ol);

    // 0) operand conversion
    cvt_w_k<<<768, 256>>>(w_qkv, (__nv_bfloat16*)wqh, (__nv_bfloat16*)wql, QKV * 256);
    cvt_w_k<<<256, 256>>>(w_out, (__nv_bfloat16*)woh, (__nv_bfloat16*)wol, 256 * 256);
    tcvt_k<<<dim3(128, 8, NB), dim3(32, 8)>>>(x, (__nv_bfloat16*)xh, (__nv_bfloat16*)xl,
                                              (long)1048576);

    // 1) qkv projection
    mma_gemm_k<<<dim3(32, 6, NB), 256, MG_SMEM>>>(
        (const __nv_bfloat16*)wqh, (const __nv_bfloat16*)wql,
        (const __nv_bfloat16*)xh, (const __nv_bfloat16*)xl,
        (float*)yb, b_qkv, (long)SS * 256, (long)QKV * SS);

    // 2) q/k straight converts (raw reshape flat view) + vT transpose convert
    qkcvt_k<<<8192, 256>>>();
    vtcvt_k<<<dim3(128, 8, NB), dim3(32, 8)>>>();

    // 3) landmarks + landmark converts
    landmarks_k<<<dim3(NB, 64), 256>>>();
    cvt_land_k<<<512, 256>>>();

    // 4) attention GEMMs (tensor)
    s1_mma_k<<<dim3(32, NB), 256, 2 * S1_STAGE>>>();
    colstats_part_k<<<dim3(8, NB), 256>>>();
    colstats_comb_k<<<NB, 64>>>();
    s3_mma_k<<<dim3(32, NB), 256, 2 * S1_STAGE>>>();
    softmax_s3_k<<<dim3(16, NB), 256>>>();
    t3_mma_k<<<dim3(16, NB), 256, T3_SMEM>>>();
    t3_reduce_k<<<512, 256>>>();
    k2inv_k<<<NB, 1024, K2INV_SMEM_FLOATS * (int)sizeof(float)>>>();
    out_mma_k<<<dim3(32, NB), 256, OUT_SMEM>>>();

    // 5) output projection
    tcvt_k<<<dim3(128, 8, NB), dim3(32, 8)>>>((const float*)ob,
        (__nv_bfloat16*)oh, (__nv_bfloat16*)ol, (long)1048576);
    mma_gemm_k<<<dim3(32, 2, NB), 256, MG_SMEM>>>(
        (const __nv_bfloat16*)woh, (const __nv_bfloat16*)wol,
        (const __nv_bfloat16*)oh, (const __nv_bfloat16*)ol,
        out, b_out, (long)SS * 256, (long)256 * SS);
}

// round 13
// speedup vs baseline: 1.1746x; 1.1746x over previous
#include <cuda_runtime.h>
#include <cuda_bf16.h>
#include <cstdint>
#include <math.h>

#define NB   8
#define EE   256
#define LL   64
#define SS   4096
#define QKV  768

// ---------------- scratch ----------------
__device__ float g_Y[NB * QKV * SS];
__device__ float g_qland[NB * LL * EE];
__device__ float g_kland[NB * LL * EE];
__device__ float g_S1[NB * SS * LL];
__device__ float g_pmax[NB * 8 * LL];
__device__ float g_psum[NB * 8 * LL];
__device__ float g_m[NB * LL];
__device__ float g_sinv[NB * LL];
__device__ float g_S3[NB * LL * SS];
__device__ float g_T3p[NB * 16 * LL * EE];
__device__ float g_T3[NB * LL * EE];
__device__ float g_O[NB * SS * EE];

// split-bf16 operands
__device__ __nv_bfloat16 g_wqh[QKV * 256], g_wql[QKV * 256];
__device__ __nv_bfloat16 g_woh[256 * 256], g_wol[256 * 256];
__device__ __nv_bfloat16 g_xh[NB * SS * 256], g_xl[NB * SS * 256];
__device__ __nv_bfloat16 g_oh[NB * SS * 256], g_ol[NB * SS * 256];
__device__ __nv_bfloat16 g_qbh[NB * SS * 256], g_qbl[NB * SS * 256];
__device__ __nv_bfloat16 g_kbh[NB * SS * 256], g_kbl[NB * SS * 256];
__device__ __nv_bfloat16 g_vth[NB * 256 * SS], g_vtl[NB * 256 * SS];
__device__ __nv_bfloat16 g_qlbh[NB * LL * 256], g_qlbl[NB * LL * 256];
__device__ __nv_bfloat16 g_klbh[NB * LL * 256], g_klbl[NB * LL * 256];
__device__ __nv_bfloat16 g_M2h[NB * 256 * LL], g_M2l[NB * 256 * LL];

__device__ __forceinline__ uint32_t smem_u32(const void* p) {
    uint32_t a;
    asm("{ .reg .u64 t; cvta.to.shared.u64 t, %1; cvt.u32.u64 %0, t; }" : "=r"(a) : "l"(p));
    return a;
}
__device__ __forceinline__ void mma_bf16(float* d, uint32_t a0, uint32_t a1, uint32_t a2,
                                         uint32_t a3, uint32_t b0, uint32_t b1) {
    asm volatile(
        "mma.sync.aligned.m16n8k16.row.col.f32.bf16.bf16.f32 "
        "{%0,%1,%2,%3}, {%4,%5,%6,%7}, {%8,%9}, {%0,%1,%2,%3};"
        : "+f"(d[0]), "+f"(d[1]), "+f"(d[2]), "+f"(d[3])
        : "r"(a0), "r"(a1), "r"(a2), "r"(a3), "r"(b0), "r"(b1));
}
__device__ __forceinline__ uint32_t pack2(float a, float b) {
    __nv_bfloat162 h = __floats2bfloat162_rn(a, b);
    return *(uint32_t*)&h;
}
#define CPA16(d, s) asm volatile("cp.async.cg.shared.global [%0], [%1], 16;" :: "r"(d), "l"(s))
#define CPA_COMMIT() asm volatile("cp.async.commit_group;" ::: "memory")
#define CPA_WAIT0()  asm volatile("cp.async.wait_group 0;" ::: "memory")
#define CPA_WAIT1()  asm volatile("cp.async.wait_group 1;" ::: "memory")

// ================= big split-bf16 GEMM (verified R5) =================
#define MG_STAGE 40960
#define MG_SMEM  (2 * MG_STAGE)
__global__ __launch_bounds__(256, 2) void mma_gemm_k(
    const __nv_bfloat16* __restrict__ Ah, const __nv_bfloat16* __restrict__ Al,
    const __nv_bfloat16* __restrict__ Bh, const __nv_bfloat16* __restrict__ Bl,
    float* __restrict__ C, const float* __restrict__ bias,
    long bStride, long cStride)
{
    extern __shared__ char smc[];
    const int tid = threadIdx.x;
    const int lane = tid & 31, wid = tid >> 5;
    const int wm = wid >> 2, ws = wid & 3;
    const int gid = lane >> 2, tg = lane & 3;
    const int n = blockIdx.z;
    const int m0 = blockIdx.y * 128, s0 = blockIdx.x * 128;

    const __nv_bfloat16* gsrc[4];
    gsrc[0] = Ah + (long)m0 * 256;
    gsrc[1] = Al + (long)m0 * 256;
    gsrc[2] = Bh + (long)n * bStride + (long)s0 * 256;
    gsrc[3] = Bl + (long)n * bStride + (long)s0 * 256;

    float acc[4][4][4];
#pragma unroll
    for (int a = 0; a < 4; a++)
#pragma unroll
        for (int b = 0; b < 4; b++)
#pragma unroll
            for (int c = 0; c < 4; c++) acc[a][b][c] = 0.f;

    auto issue = [&](int c, int buf) {
#pragma unroll
        for (int it = 0; it < 8; it++) {
            int idx = tid + it * 256;
            int mat = idx >> 9, rr = (idx >> 2) & 127, seg = idx & 3;
            uint32_t d = smem_u32(smc + buf * MG_STAGE + mat * 10240 + rr * 80 + seg * 16);
            const __nv_bfloat16* s = gsrc[mat] + rr * 256 + c * 32 + seg * 8;
            CPA16(d, s);
        }
        CPA_COMMIT();
    };

    issue(0, 0);
    for (int c = 0; c < 8; c++) {
        if (c < 7) { issue(c + 1, (c + 1) & 1); CPA_WAIT1(); }
        else CPA_WAIT0();
        __syncthreads();
        const char* st = smc + (c & 1) * MG_STAGE;
#pragma unroll
        for (int ks = 0; ks < 2; ks++) {
            uint32_t bh[4][2], bl[4][2];
#pragma unroll
            for (int nt = 0; nt < 4; nt++) {
                int nrow = ws * 32 + nt * 8 + gid;
                const char* pb = st + 20480 + nrow * 80 + (ks * 16 + tg * 2) * 2;
                bh[nt][0] = *(const uint32_t*)pb;
                bh[nt][1] = *(const uint32_t*)(pb + 16);
                bl[nt][0] = *(const uint32_t*)(pb + 10240);
                bl[nt][1] = *(const uint32_t*)(pb + 10256);
            }
#pragma unroll
            for (int mt = 0; mt < 4; mt++) {
                int arow = wm * 64 + mt * 16 + gid;
                const char* pa = st + arow * 80 + (ks * 16 + tg * 2) * 2;
                uint32_t ah0 = *(const uint32_t*)pa;
                uint32_t ah1 = *(const uint32_t*)(pa + 640);
                uint32_t ah2 = *(const uint32_t*)(pa + 16);
                uint32_t ah3 = *(const uint32_t*)(pa + 656);
                uint32_t al0 = *(const uint32_t*)(pa + 10240);
                uint32_t al1 = *(const uint32_t*)(pa + 10880);
                uint32_t al2 = *(const uint32_t*)(pa + 10256);
                uint32_t al3 = *(const uint32_t*)(pa + 10896);
#pragma unroll
                for (int nt = 0; nt < 4; nt++) {
                    mma_bf16(acc[mt][nt], ah0, ah1, ah2, ah3, bh[nt][0], bh[nt][1]);
                    mma_bf16(acc[mt][nt], ah0, ah1, ah2, ah3, bl[nt][0], bl[nt][1]);
                    mma_bf16(acc[mt][nt], al0, al1, al2, al3, bh[nt][0], bh[nt][1]);
                }
            }
        }
        __syncthreads();
    }

    float* Cn = C + (long)n * cStride;
#pragma unroll
    for (int mt = 0; mt < 4; mt++) {
        int r0 = m0 + wm * 64 + mt * 16 + gid;
        float b0v = bias[r0], b1v = bias[r0 + 8];
#pragma unroll
        for (int nt = 0; nt < 4; nt++) {
            int col = s0 + ws * 32 + nt * 8 + tg * 2;
            *(float2*)(Cn + (long)r0 * 4096 + col) =
                make_float2(acc[mt][nt][0] + b0v, acc[mt][nt][1] + b0v);
            *(float2*)(Cn + (long)(r0 + 8) * 4096 + col) =
                make_float2(acc[mt][nt][2] + b1v, acc[mt][nt][3] + b1v);
        }
    }
}

// ================= converts =================
__global__ void cvt_w_k(const float* __restrict__ src, __nv_bfloat16* __restrict__ hi,
                        __nv_bfloat16* __restrict__ lo, int nElem)
{
    int i = blockIdx.x * 256 + threadIdx.x;
    if (i < nElem) {
        float v = src[i];
        __nv_bfloat16 h = __float2bfloat16(v);
        hi[i] = h;
        lo[i] = __float2bfloat16(v - __bfloat162float(h));
    }
}

__global__ void tcvt_k(const float* __restrict__ src, __nv_bfloat16* __restrict__ hi,
                       __nv_bfloat16* __restrict__ lo, long srcBatchStride)
{
    __shared__ float t[32][33];
    int n = blockIdx.z;
    const float* S = src + (long)n * srcBatchStride;
    int s0 = blockIdx.x * 32, k0 = blockIdx.y * 32;
    int tx = threadIdx.x, ty = threadIdx.y;
#pragma unroll
    for (int i = 0; i < 32; i += 8) t[ty + i][tx] = S[(long)(k0 + ty + i) * 4096 + s0 + tx];
    __syncthreads();
    long base = (long)n * 1048576;
#pragma unroll
    for (int i = 0; i < 32; i += 8) {
        float v = t[tx][ty + i];
        __nv_bfloat16 h = __float2bfloat16(v);
        long o = base + (long)(s0 + ty + i) * 256 + k0 + tx;
        hi[o] = h;
        lo[o] = __float2bfloat16(v - __bfloat162float(h));
    }
}

// fused: q/k flat-view bf16 split converts + landmark means + landmark bf16 converts
__global__ __launch_bounds__(256) void qkland_k()
{
    int n = blockIdx.x, l = blockIdx.y, e = threadIdx.x;
    const float* base = g_Y + (long)n * 3145728 + (long)l * 64 * 768;
    float aq = 0.f, ak = 0.f;
    long obase = ((long)n * 4096 + l * 64) * 256 + e;
#pragma unroll 4
    for (int r = 0; r < 64; r++) {
        float q = base[r * 768 + e];
        float k = base[r * 768 + 256 + e];
        aq += q; ak += k;
        __nv_bfloat16 qh = __float2bfloat16(q);
        __nv_bfloat16 kh = __float2bfloat16(k);
        long o = obase + (long)r * 256;
        g_qbh[o] = qh; g_qbl[o] = __float2bfloat16(q - __bfloat162float(qh));
        g_kbh[o] = kh; g_kbl[o] = __float2bfloat16(k - __bfloat162float(kh));
    }
    int idx = (n * 64 + l) * 256 + e;
    float ql = aq * (1.f / 4096.f), kl = ak * (1.f / 4096.f);
    g_qland[idx] = ql; g_kland[idx] = kl;
    __nv_bfloat16 qlh = __float2bfloat16(ql), klh = __float2bfloat16(kl);
    g_qlbh[idx] = qlh; g_qlbl[idx] = __float2bfloat16(ql - __bfloat162float(qlh));
    g_klbh[idx] = klh; g_klbl[idx] = __float2bfloat16(kl - __bfloat162float(klh));
}

// vT transpose convert: vT[n][e][s] = Yflat[n][s*768 + 512 + e]
__global__ void vtcvt_k()
{
    __shared__ float t[32][33];
    int n = blockIdx.z;
    int s0 = blockIdx.x * 32, e0 = blockIdx.y * 32;
    int tx = threadIdx.x, ty = threadIdx.y;
    const float* S = g_Y + (long)n * 3145728;
#pragma unroll
    for (int i = 0; i < 32; i += 8)
        t[ty + i][tx] = S[(long)(s0 + ty + i) * 768 + 512 + e0 + tx];
    __syncthreads();
    long base = (long)n * 1048576;
#pragma unroll
    for (int i = 0; i < 32; i += 8) {
        float v = t[tx][ty + i];
        __nv_bfloat16 h = __float2bfloat16(v);
        long o = base + (long)(e0 + ty + i) * 4096 + s0 + tx;
        g_vth[o] = h;
        g_vtl[o] = __float2bfloat16(v - __bfloat162float(h));
    }
}

// ================= S1 (verified R10) =================
#define S1_STAGE 30720
__global__ __launch_bounds__(256, 2) void s1_mma_k()
{
    extern __shared__ char smc[];
    int tid = threadIdx.x, lane = tid & 31, wid = tid >> 5;
    int wm = wid >> 1, ws = wid & 1, gid = lane >> 2, tg = lane & 3;
    int n = blockIdx.y, i0 = blockIdx.x * 128;
    const __nv_bfloat16* Ah = g_qbh + (long)n * 1048576 + (long)i0 * 256;
    const __nv_bfloat16* Al = g_qbl + (long)n * 1048576 + (long)i0 * 256;
    const __nv_bfloat16* Bh = g_klbh + n * 16384;
    const __nv_bfloat16* Bl = g_klbl + n * 16384;

    float acc[2][4][4];
#pragma unroll
    for (int a = 0; a < 2; a++)
#pragma unroll
        for (int b = 0; b < 4; b++)
#pragma unroll
            for (int c = 0; c < 4; c++) acc[a][b][c] = 0.f;

    auto issue = [&](int c, int buf) {
#pragma unroll
        for (int it = 0; it < 6; it++) {
            int idx = tid + it * 256;
            uint32_t d; const __nv_bfloat16* s;
            if (idx < 1024) {
                int half = idx >> 9, r = (idx >> 2) & 127, seg = idx & 3;
                d = smem_u32(smc + buf * S1_STAGE + half * 10240 + r * 80 + seg * 16);
                s = (half ? Al : Ah) + r * 256 + c * 32 + seg * 8;
            } else {
                int j = idx - 1024;
                int half = j >> 8, r = (j >> 2) & 63, seg = j & 3;
                d = smem_u32(smc + buf * S1_STAGE + 20480 + half * 5120 + r * 80 + seg * 16);
                s = (half ? Bl : Bh) + r * 256 + c * 32 + seg * 8;
            }
            CPA16(d, s);
        }
        CPA_COMMIT();
    };

    issue(0, 0);
    for (int c = 0; c < 8; c++) {
        if (c < 7) { issue(c + 1, (c + 1) & 1); CPA_WAIT1(); }
        else CPA_WAIT0();
        __syncthreads();
        const char* st = smc + (c & 1) * S1_STAGE;
#pragma unroll
        for (int ks = 0; ks < 2; ks++) {
            uint32_t bh[4][2], bl[4][2];
#pragma unroll
            for (int nt = 0; nt < 4; nt++) {
                int nrow = ws * 32 + nt * 8 + gid;
                const char* pb = st + 20480 + nrow * 80 + (ks * 16 + tg * 2) * 2;
                bh[nt][0] = *(const uint32_t*)pb;
                bh[nt][1] = *(const uint32_t*)(pb + 16);
                bl[nt][0] = *(const uint32_t*)(pb + 5120);
                bl[nt][1] = *(const uint32_t*)(pb + 5136);
            }
#pragma unroll
            for (int mt = 0; mt < 2; mt++) {
                int arow = wm * 32 + mt * 16 + gid;
                const char* pa = st + arow * 80 + (ks * 16 + tg * 2) * 2;
                uint32_t ah0 = *(const uint32_t*)pa;
                uint32_t ah1 = *(const uint32_t*)(pa + 640);
                uint32_t ah2 = *(const uint32_t*)(pa + 16);
                uint32_t ah3 = *(const uint32_t*)(pa + 656);
                uint32_t al0 = *(const uint32_t*)(pa + 10240);
                uint32_t al1 = *(const uint32_t*)(pa + 10880);
                uint32_t al2 = *(const uint32_t*)(pa + 10256);
                uint32_t al3 = *(const uint32_t*)(pa + 10896);
#pragma unroll
                for (int nt = 0; nt < 4; nt++) {
                    mma_bf16(acc[mt][nt], ah0, ah1, ah2, ah3, bh[nt][0], bh[nt][1]);
                    mma_bf16(acc[mt][nt], ah0, ah1, ah2, ah3, bl[nt][0], bl[nt][1]);
                    mma_bf16(acc[mt][nt], al0, al1, al2, al3, bh[nt][0], bh[nt][1]);
                }
            }
        }
        __syncthreads();
    }
#pragma unroll
    for (int mt = 0; mt < 2; mt++) {
        int r0 = i0 + wm * 32 + mt * 16 + gid;
#pragma unroll
        for (int nt = 0; nt < 4; nt++) {
            int col = ws * 32 + nt * 8 + tg * 2;
            float* dst = g_S1 + ((long)n * 4096 + r0) * 64 + col;
            *(float2*)dst = make_float2(acc[mt][nt][0], acc[mt][nt][1]);
            *(float2*)(dst + 512) = make_float2(acc[mt][nt][2], acc[mt][nt][3]);
        }
    }
}

// ================= S3 (verified R10) =================
__global__ __launch_bounds__(256, 2) void s3_mma_k()
{
    extern __shared__ char smc[];
    int tid = threadIdx.x, lane = tid & 31, wid = tid >> 5;
    int wm = wid >> 2, ws = wid & 3, gid = lane >> 2, tg = lane & 3;
    int n = blockIdx.y, s0 = blockIdx.x * 128;
    const __nv_bfloat16* Ah = g_qlbh + n * 16384;
    const __nv_bfloat16* Al = g_qlbl + n * 16384;
    const __nv_bfloat16* Bh = g_kbh + (long)n * 1048576 + (long)s0 * 256;
    const __nv_bfloat16* Bl = g_kbl + (long)n * 1048576 + (long)s0 * 256;

    float acc[2][4][4];
#pragma unroll
    for (int a = 0; a < 2; a++)
#pragma unroll
        for (int b = 0; b < 4; b++)
#pragma unroll
            for (int c = 0; c < 4; c++) acc[a][b][c] = 0.f;

    auto issue = [&](int c, int buf) {
#pragma unroll
        for (int it = 0; it < 6; it++) {
            int idx = tid + it * 256;
            uint32_t d; const __nv_bfloat16* s;
            if (idx < 512) {
                int half = idx >> 8, r = (idx >> 2) & 63, seg = idx & 3;
                d = smem_u32(smc + buf * S1_STAGE + half * 5120 + r * 80 + seg * 16);
                s = (half ? Al : Ah) + r * 256 + c * 32 + seg * 8;
            } else {
                int j = idx - 512;
                int half = j >> 9, r = (j >> 2) & 127, seg = j & 3;
                d = smem_u32(smc + buf * S1_STAGE + 10240 + half * 10240 + r * 80 + seg * 16);
                s = (half ? Bl : Bh) + r * 256 + c * 32 + seg * 8;
            }
            CPA16(d, s);
        }
        CPA_COMMIT();
    };

    issue(0, 0);
    for (int c = 0; c < 8; c++) {
        if (c < 7) { issue(c + 1, (c + 1) & 1); CPA_WAIT1(); }
        else CPA_WAIT0();
        __syncthreads();
        const char* st = smc + (c & 1) * S1_STAGE;
#pragma unroll
        for (int ks = 0; ks < 2; ks++) {
            uint32_t bh[4][2], bl[4][2];
#pragma unroll
            for (int nt = 0; nt < 4; nt++) {
                int nrow = ws * 32 + nt * 8 + gid;
                const char* pb = st + 10240 + nrow * 80 + (ks * 16 + tg * 2) * 2;
                bh[nt][0] = *(const uint32_t*)pb;
                bh[nt][1] = *(const uint32_t*)(pb + 16);
                bl[nt][0] = *(const uint32_t*)(pb + 10240);
                bl[nt][1] = *(const uint32_t*)(pb + 10256);
            }
#pragma unroll
            for (int mt = 0; mt < 2; mt++) {
                int arow = wm * 32 + mt * 16 + gid;
                const char* pa = st + arow * 80 + (ks * 16 + tg * 2) * 2;
                uint32_t ah0 = *(const uint32_t*)pa;
                uint32_t ah1 = *(const uint32_t*)(pa + 640);
                uint32_t ah2 = *(const uint32_t*)(pa + 16);
                uint32_t ah3 = *(const uint32_t*)(pa + 656);
                uint32_t al0 = *(const uint32_t*)(pa + 5120);
                uint32_t al1 = *(const uint32_t*)(pa + 5760);
                uint32_t al2 = *(const uint32_t*)(pa + 5136);
                uint32_t al3 = *(const uint32_t*)(pa + 5776);
#pragma unroll
                for (int nt = 0; nt < 4; nt++) {
                    mma_bf16(acc[mt][nt], ah0, ah1, ah2, ah3, bh[nt][0], bh[nt][1]);
                    mma_bf16(acc[mt][nt], ah0, ah1, ah2, ah3, bl[nt][0], bl[nt][1]);
                    mma_bf16(acc[mt][nt], al0, al1, al2, al3, bh[nt][0], bh[nt][1]);
                }
            }
        }
        __syncthreads();
    }
#pragma unroll
    for (int mt = 0; mt < 2; mt++) {
        int r0 = wm * 32 + mt * 16 + gid;
#pragma unroll
        for (int nt = 0; nt < 4; nt++) {
            int col = s0 + ws * 32 + nt * 8 + tg * 2;
            float* dst = g_S3 + (long)n * 262144 + (long)r0 * 4096 + col;
            *(float2*)dst = make_float2(acc[mt][nt][0], acc[mt][nt][1]);
            *(float2*)(dst + 8 * 4096) = make_float2(acc[mt][nt][2], acc[mt][nt][3]);
        }
    }
}

// ================= softmax helpers =================
__global__ void colstats_part_k()
{
    __shared__ float sm2[4][64];
    int stripe = blockIdx.x, n = blockIdx.y;
    int tid = threadIdx.x;
    int j = tid & 63, g = tid >> 6;
    const float* S = g_S1 + (long)n * SS * 64;
    float m = -1e30f;
    for (int i = stripe * 512 + g; i < stripe * 512 + 512; i += 4)
        m = fmaxf(m, S[(long)i * 64 + j]);
    sm2[g][j] = m;
    __syncthreads();
    float mm = fmaxf(fmaxf(sm2[0][j], sm2[1][j]), fmaxf(sm2[2][j], sm2[3][j]));
    float s = 0.f;
    for (int i = stripe * 512 + g; i < stripe * 512 + 512; i += 4)
        s += expf(S[(long)i * 64 + j] - mm);
    __syncthreads();
    sm2[g][j] = s;
    __syncthreads();
    if (g == 0) {
        float ss = sm2[0][j] + sm2[1][j] + sm2[2][j] + sm2[3][j];
        g_pmax[(n * 8 + stripe) * 64 + j] = mm;
        g_psum[(n * 8 + stripe) * 64 + j] = ss;
    }
}

__global__ void colstats_comb_k()
{
    int n = blockIdx.x, j = threadIdx.x;
    float m = -1e30f;
#pragma unroll
    for (int c = 0; c < 8; c++) m = fmaxf(m, g_pmax[(n * 8 + c) * 64 + j]);
    float s = 0.f;
#pragma unroll
    for (int c = 0; c < 8; c++)
        s += g_psum[(n * 8 + c) * 64 + j] * expf(g_pmax[(n * 8 + c) * 64 + j] - m);
    g_m[n * 64 + j] = m;
    g_sinv[n * 64 + j] = 1.f / s;
}

__global__ void softmax_s3_k()
{
    int n = blockIdx.y;
    int s = blockIdx.x * 256 + threadIdx.x;
    float* S = g_S3 + (long)n * LL * SS;
    float v[64];
    float m = -1e30f;
#pragma unroll
    for (int j = 0; j < 64; j++) { v[j] = S[(long)j * SS + s]; m = fmaxf(m, v[j]); }
    float sum = 0.f;
#pragma unroll
    for (int j = 0; j < 64; j++) { v[j] = expf(v[j] - m); sum += v[j]; }
    float r = 1.f / sum;
#pragma unroll
    for (int j = 0; j < 64; j++) S[(long)j * SS + s] = v[j] * r;
}

// ================= T3 (verified R10) =================
#define T3_SMEM 51200
__global__ __launch_bounds__(256, 2) void t3_mma_k()
{
    extern __shared__ char smc[];
    int tid = threadIdx.x, lane = tid & 31, wid = tid >> 5;
    int wm = wid >> 2, ws = wid & 3, gid = lane >> 2, tg = lane & 3;
    int n = blockIdx.y, s0 = blockIdx.x * 256;

    float acc[2][8][4];
#pragma unroll
    for (int a = 0; a < 2; a++)
#pragma unroll
        for (int b = 0; b < 8; b++)
#pragma unroll
            for (int c = 0; c < 4; c++) acc[a][b][c] = 0.f;

    for (int cc = 0; cc < 8; cc++) {
        {
            int j = tid >> 2, kq = (tid & 3) * 8;
            const float* s = g_S3 + (long)n * 262144 + (long)j * 4096 + s0 + cc * 32 + kq;
            float4 f0 = *(const float4*)s, f1 = *(const float4*)(s + 4);
            float v[8] = {f0.x, f0.y, f0.z, f0.w, f1.x, f1.y, f1.z, f1.w};
            uint32_t hi[4], lo[4];
#pragma unroll
            for (int p = 0; p < 4; p++) {
                __nv_bfloat16 h0 = __float2bfloat16(v[2 * p]);
                __nv_bfloat16 h1 = __float2bfloat16(v[2 * p + 1]);
                hi[p] = pack2(__bfloat162float(h0), __bfloat162float(h1));
                lo[p] = pack2(v[2 * p] - __bfloat162float(h0), v[2 * p + 1] - __bfloat162float(h1));
            }
            *(uint4*)(smc + 40960 + j * 80 + (kq >> 3) * 16) = *(uint4*)hi;
            *(uint4*)(smc + 46080 + j * 80 + (kq >> 3) * 16) = *(uint4*)lo;
        }
#pragma unroll
        for (int it = 0; it < 8; it++) {
            int idx = tid + it * 256;
            int half = idx >> 10, r = (idx >> 2) & 255, seg = idx & 3;
            uint32_t d = smem_u32(smc + half * 20480 + r * 80 + seg * 16);
            const __nv_bfloat16* s = (half ? g_vtl : g_vth) +
                (long)n * 1048576 + (long)r * 4096 + s0 + cc * 32 + seg * 8;
            CPA16(d, s);
        }
        CPA_COMMIT();
        CPA_WAIT0();
        __syncthreads();
#pragma unroll
        for (int ks = 0; ks < 2; ks++) {
            uint32_t bh[8][2], bl[8][2];
#pragma unroll
            for (int nt = 0; nt < 8; nt++) {
                int nrow = ws * 64 + nt * 8 + gid;
                const char* pb = smc + nrow * 80 + (ks * 16 + tg * 2) * 2;
                bh[nt][0] = *(const uint32_t*)pb;
                bh[nt][1] = *(const uint32_t*)(pb + 16);
                bl[nt][0] = *(const uint32_t*)(pb + 20480);
                bl[nt][1] = *(const uint32_t*)(pb + 20496);
            }
#pragma unroll
            for (int mt = 0; mt < 2; mt++) {
                int arow = wm * 32 + mt * 16 + gid;
                const char* pa = smc + 40960 + arow * 80 + (ks * 16 + tg * 2) * 2;
                uint32_t ah0 = *(const uint32_t*)pa;
                uint32_t ah1 = *(const uint32_t*)(pa + 640);
                uint32_t ah2 = *(const uint32_t*)(pa + 16);
                uint32_t ah3 = *(const uint32_t*)(pa + 656);
                uint32_t al0 = *(const uint32_t*)(pa + 5120);
                uint32_t al1 = *(const uint32_t*)(pa + 5760);
                uint32_t al2 = *(const uint32_t*)(pa + 5136);
                uint32_t al3 = *(const uint32_t*)(pa + 5776);
#pragma unroll
                for (int nt = 0; nt < 8; nt++) {
                    mma_bf16(acc[mt][nt], ah0, ah1, ah2, ah3, bh[nt][0], bh[nt][1]);
                    mma_bf16(acc[mt][nt], ah0, ah1, ah2, ah3, bl[nt][0], bl[nt][1]);
                    mma_bf16(acc[mt][nt], al0, al1, al2, al3, bh[nt][0], bh[nt][1]);
                }
            }
        }
        __syncthreads();
    }
    float* dst = g_T3p + (long)(n * 16 + blockIdx.x) * 16384;
#pragma unroll
    for (int mt = 0; mt < 2; mt++) {
        int r0 = wm * 32 + mt * 16 + gid;
#pragma unroll
        for (int nt = 0; nt < 8; nt++) {
            int col = ws * 64 + nt * 8 + tg * 2;
            *(float2*)(dst + r0 * 256 + col) = make_float2(acc[mt][nt][0], acc[mt][nt][1]);
            *(float2*)(dst + (r0 + 8) * 256 + col) = make_float2(acc[mt][nt][2], acc[mt][nt][3]);
        }
    }
}

__global__ void t3_reduce_k()
{
    int idx = blockIdx.x * 256 + threadIdx.x;
    int n = idx >> 14;
    int r = idx & 16383;
    const float* p = g_T3p + (long)n * 16 * 16384 + r;
    float s = 0.f;
#pragma unroll
    for (int c = 0; c < 16; c++) s += p[(long)c * 16384];
    g_T3[idx] = s;
}

// ================= k2inv v2: tiled S2 / NS mm64v2 / tiled M2s =================
#define KV_K2   0
#define KV_VV   4096
#define KV_BA   8192
#define KV_BB   12288
#define KV_BC   16384
#define KV_P    20480
#define KV_QLS  32768
#define KV_KTS  34816
#define KV_RED  36992
#define KV_T3S  8192
#define K2INV_SMEM_FLOATS 37184

// D[64][64] = A[64][64] @ B[64][64], all row-major in smem. 1024 threads, 4-way K split.
__device__ __forceinline__ void mm64v2(float* D, const float* A, const float* B,
                                       float* P, int tid)
{
    int kg = tid >> 8;
    int t = tid & 255;
    int r0 = (t >> 4) * 4;
    int c0 = (t & 15) * 4;
    int kb = kg * 16;
    float acc[4][4];
#pragma unroll
    for (int a = 0; a < 4; a++)
#pragma unroll
        for (int b = 0; b < 4; b++) acc[a][b] = 0.f;

#pragma unroll
    for (int kk = 0; kk < 16; kk += 4) {
        float4 av[4];
#pragma unroll
        for (int rr = 0; rr < 4; rr++)
            av[rr] = *(const float4*)&A[(r0 + rr) * 64 + kb + kk];
#pragma unroll
        for (int kq = 0; kq < 4; kq++) {
            float4 b = *(const float4*)&B[(kb + kk + kq) * 64 + c0];
#pragma unroll
            for (int rr = 0; rr < 4; rr++) {
                float aw = reinterpret_cast<const float*>(&av[rr])[kq];
                acc[rr][0] += aw * b.x; acc[rr][1] += aw * b.y;
                acc[rr][2] += aw * b.z; acc[rr][3] += aw * b.w;
            }
        }
    }
    if (kg) {
        float* Pp = P + (kg - 1) * 4096;
#pragma unroll
        for (int rr = 0; rr < 4; rr++)
            *(float4*)&Pp[(r0 + rr) * 64 + c0] =
                make_float4(acc[rr][0], acc[rr][1], acc[rr][2], acc[rr][3]);
    }
    __syncthreads();
    if (kg == 0) {
#pragma unroll
        for (int rr = 0; rr < 4; rr++) {
            float4 s = make_float4(acc[rr][0], acc[rr][1], acc[rr][2], acc[rr][3]);
#pragma unroll
            for (int g = 0; g < 3; g++) {
                float4 p = *(const float4*)&P[g * 4096 + (r0 + rr) * 64 + c0];
                s.x += p.x; s.y += p.y; s.z += p.z; s.w += p.w;
            }
            *(float4*)&D[(r0 + rr) * 64 + c0] = s;
        }
    }
    __syncthreads();
}

__global__ __launch_bounds__(1024) void k2inv_k()
{
    extern __shared__ float sm[];
    float* K2 = sm + KV_K2;
    float* Vv = sm + KV_VV;
    float* BA = sm + KV_BA;
    float* BB = sm + KV_BB;
    float* BC = sm + KV_BC;
    float* P  = sm + KV_P;
    float* QLs = sm + KV_QLS;   // [64][32]
    float* KTs = sm + KV_KTS;   // [32][68]
    float* red = sm + KV_RED;

    int n = blockIdx.x;
    int tid = threadIdx.x;
    const float* ql = g_qland + n * 16384;
    const float* kl = g_kland + n * 16384;

    // ---- S2 = qland @ kland^T, 4x4 tiles (threads<256 compute) ----
    int st = tid & 255;
    int sr0 = (st >> 4) * 4;
    int sc0 = (st & 15) * 4;
    float accS[4][4];
#pragma unroll
    for (int a = 0; a < 4; a++)
#pragma unroll
        for (int b = 0; b < 4; b++) accS[a][b] = 0.f;

    for (int e0 = 0; e0 < 256; e0 += 32) {
#pragma unroll
        for (int p = 0; p < 2; p++) {
            int t2 = tid + p * 1024;
            int r = t2 >> 5, c = t2 & 31;
            QLs[r * 32 + c] = ql[r * 256 + e0 + c];
            KTs[c * 68 + r] = kl[r * 256 + e0 + c];
        }
        __syncthreads();
        if (tid < 256) {
#pragma unroll
            for (int kk = 0; kk < 32; kk += 4) {
                float4 av[4];
#pragma unroll
                for (int rr = 0; rr < 4; rr++)
                    av[rr] = *(const float4*)&QLs[(sr0 + rr) * 32 + kk];
#pragma unroll
                for (int kq = 0; kq < 4; kq++) {
                    float4 b = *(const float4*)&KTs[(kk + kq) * 68 + sc0];
#pragma unroll
                    for (int rr = 0; rr < 4; rr++) {
                        float aw = reinterpret_cast<const float*>(&av[rr])[kq];
                        accS[rr][0] += aw * b.x; accS[rr][1] += aw * b.y;
                        accS[rr][2] += aw * b.z; accS[rr][3] += aw * b.w;
                    }
                }
            }
        }
        __syncthreads();
    }
    if (tid < 256) {
#pragma unroll
        for (int rr = 0; rr < 4; rr++)
            *(float4*)&K2[(sr0 + rr) * 64 + sc0] =
                make_float4(accS[rr][0], accS[rr][1], accS[rr][2], accS[rr][3]);
    }
    __syncthreads();

    // ---- column softmax (over i) ----
    if (tid < 64) {
        int j = tid;
        float m = -1e30f;
        for (int i = 0; i < 64; i++) m = fmaxf(m, K2[i * 64 + j]);
        float s = 0.f;
        for (int i = 0; i < 64; i++) s += expf(K2[i * 64 + j] - m);
        red[j] = m; red[64 + j] = 1.f / s;
    }
    __syncthreads();
#pragma unroll
    for (int p = 0; p < 4; p++) {
        int t = tid + p * 1024;
        int j = t & 63;
        K2[t] = expf(K2[t] - red[j]) * red[64 + j];
    }
    __syncthreads();

    // ---- V0/VI scaling ----
    if (tid < 64) {
        int i = tid;
        float rs = 0.f, cs = 0.f;
        for (int j = 0; j < 64; j++) { rs += fabsf(K2[i * 64 + j]); cs += fabsf(K2[j * 64 + i]); }
        red[i] = rs; red[64 + i] = cs;
    }
    __syncthreads();
    if (tid == 0) {
        float vi = 0.f, v0 = 0.f;
        for (int t = 0; t < 64; t++) { vi = fmaxf(vi, red[t]); v0 = fmaxf(v0, red[64 + t]); }
        red[128] = 1.f / (v0 * vi);
    }
    __syncthreads();
    float isc = red[128];
#pragma unroll
    for (int p = 0; p < 4; p++) {
        int t = tid + p * 1024;
        int a = t >> 6, b = t & 63;
        Vv[t] = K2[b * 64 + a] * isc;
    }
    __syncthreads();

    // ---- 6 Newton-Schulz iterations ----
    for (int it = 0; it < 6; it++) {
        mm64v2(BA, K2, Vv, P, tid);
        mm64v2(BB, BA, BA, P, tid);
#pragma unroll
        for (int p = 0; p < 4; p++) {
            int t = tid + p * 1024;
            float d = ((t >> 6) == (t & 63)) ? 15.f : 0.f;
            BB[t] = d - 7.f * BA[t] + BB[t];
        }
        __syncthreads();
        mm64v2(BC, BA, BB, P, tid);
#pragma unroll
        for (int p = 0; p < 4; p++) {
            int t = tid + p * 1024;
            float d = ((t >> 6) == (t & 63)) ? 13.f : 0.f;
            BC[t] = d - BC[t];
        }
        __syncthreads();
        mm64v2(BB, Vv, BC, P, tid);
#pragma unroll
        for (int p = 0; p < 4; p++) {
            int t = tid + p * 1024;
            Vv[t] = 0.25f * BB[t];
        }
        __syncthreads();
    }

    // ---- M2sT = transpose((Vv @ T3) * sinv_j), 4x4 tiles, T3 staged ----
    float* T3s = sm + KV_T3S;   // [64][256]
    for (int it = 0; it < 16; it++) {
        int idx = tid + it * 1024;
        T3s[idx] = g_T3[n * 16384 + idx];
    }
    __syncthreads();
    {
        int g = tid >> 8, t = tid & 255;
        int j0 = (t >> 4) * 4;
        int ec0 = g * 64 + (t & 15) * 4;
        float acc[4][4];
#pragma unroll
        for (int a = 0; a < 4; a++)
#pragma unroll
            for (int b = 0; b < 4; b++) acc[a][b] = 0.f;
#pragma unroll
        for (int kk = 0; kk < 64; kk += 4) {
            float4 av[4];
#pragma unroll
            for (int rr = 0; rr < 4; rr++)
                av[rr] = *(const float4*)&Vv[(j0 + rr) * 64 + kk];
#pragma unroll
            for (int kq = 0; kq < 4; kq++) {
                float4 b = *(const float4*)&T3s[(kk + kq) * 256 + ec0];
#pragma unroll
                for (int rr = 0; rr < 4; rr++) {
                    float aw = reinterpret_cast<const float*>(&av[rr])[kq];
                    acc[rr][0] += aw * b.x; acc[rr][1] += aw * b.y;
                    acc[rr][2] += aw * b.z; acc[rr][3] += aw * b.w;
                }
            }
        }
#pragma unroll
        for (int rr = 0; rr < 4; rr++) {
            float sv = g_sinv[n * 64 + j0 + rr];
#pragma unroll
            for (int cc = 0; cc < 4; cc++) {
                float a = acc[rr][cc] * sv;
                __nv_bfloat16 h = __float2bfloat16(a);
                long o = (long)n * 16384 + (long)(ec0 + cc) * 64 + j0 + rr;
                g_M2h[o] = h;
                g_M2l[o] = __float2bfloat16(a - __bfloat162float(h));
            }
        }
    }
}

// ================= out (verified R10) =================
#define OUT_SMEM 61696
__global__ __launch_bounds__(256, 1) void out_mma_k()
{
    extern __shared__ char smc[];
    float* ms = (float*)smc;
    int tid = threadIdx.x, lane = tid & 31, wid = tid >> 5;
    int wm = wid >> 2, ws = wid & 3, gid = lane >> 2, tg = lane & 3;
    int n = blockIdx.y, i0 = blockIdx.x * 128;

    if (tid < 64) ms[tid] = g_m[n * 64 + tid];
    __syncthreads();

    float acc[4][8][4];
#pragma unroll
    for (int a = 0; a < 4; a++)
#pragma unroll
        for (int b = 0; b < 8; b++)
#pragma unroll
            for (int c = 0; c < 4; c++) acc[a][b][c] = 0.f;

    for (int c = 0; c < 2; c++) {
        if (c) __syncthreads();
        {
            int row = tid >> 1, kq = (tid & 1) * 16;
            const float* Sr = g_S1 + ((long)n * 4096 + i0 + row) * 64 + c * 32 + kq;
            float v[16];
            *(float4*)&v[0]  = *(const float4*)Sr;
            *(float4*)&v[4]  = *(const float4*)(Sr + 4);
            *(float4*)&v[8]  = *(const float4*)(Sr + 8);
            *(float4*)&v[12] = *(const float4*)(Sr + 12);
            uint32_t hi[8], lo[8];
#pragma unroll
            for (int p = 0; p < 8; p++) {
                float e0 = expf(v[2 * p] - ms[c * 32 + kq + 2 * p]);
                float e1 = expf(v[2 * p + 1] - ms[c * 32 + kq + 2 * p + 1]);
                __nv_bfloat16 h0 = __float2bfloat16(e0), h1 = __float2bfloat16(e1);
                hi[p] = pack2(__bfloat162float(h0), __bfloat162float(h1));
                lo[p] = pack2(e0 - __bfloat162float(h0), e1 - __bfloat162float(h1));
            }
            char* pa = smc + 256 + row * 80 + (kq >> 3) * 16;
            *(uint4*)pa = *(uint4*)hi;
            *(uint4*)(pa + 16) = *(uint4*)&hi[4];
            char* pl = smc + 10496 + row * 80 + (kq >> 3) * 16;
            *(uint4*)pl = *(uint4*)lo;
            *(uint4*)(pl + 16) = *(uint4*)&lo[4];
        }
#pragma unroll
        for (int it = 0; it < 8; it++) {
            int idx = tid + it * 256;
            int half = idx >> 10, r = (idx >> 2) & 255, seg = idx & 3;
            uint32_t d = smem_u32(smc + 20736 + half * 20480 + r * 80 + seg * 16);
            const __nv_bfloat16* s = (half ? g_M2l : g_M2h) + n * 16384 + r * 64 + c * 32 + seg * 8;
            CPA16(d, s);
        }
        CPA_COMMIT();
        CPA_WAIT0();
        __syncthreads();
#pragma unroll
        for (int ks = 0; ks < 2; ks++) {
            uint32_t bh[8][2], bl[8][2];
#pragma unroll
            for (int nt = 0; nt < 8; nt++) {
                int nrow = ws * 64 + nt * 8 + gid;
                const char* pb = smc + 20736 + nrow * 80 + (ks * 16 + tg * 2) * 2;
                bh[nt][0] = *(const uint32_t*)pb;
                bh[nt][1] = *(const uint32_t*)(pb + 16);
                bl[nt][0] = *(const uint32_t*)(pb + 20480);
                bl[nt][1] = *(const uint32_t*)(pb + 20496);
            }
#pragma unroll
            for (int mt = 0; mt < 4; mt++) {
                int arow = wm * 64 + mt * 16 + gid;
                const char* pa = smc + 256 + arow * 80 + (ks * 16 + tg * 2) * 2;
                uint32_t ah0 = *(const uint32_t*)pa;
                uint32_t ah1 = *(const uint32_t*)(pa + 640);
                uint32_t ah2 = *(const uint32_t*)(pa + 16);
                uint32_t ah3 = *(const uint32_t*)(pa + 656);
                uint32_t al0 = *(const uint32_t*)(pa + 10240);
                uint32_t al1 = *(const uint32_t*)(pa + 10880);
                uint32_t al2 = *(const uint32_t*)(pa + 10256);
                uint32_t al3 = *(const uint32_t*)(pa + 10896);
#pragma unroll
                for (int nt = 0; nt < 8; nt++) {
                    mma_bf16(acc[mt][nt], ah0, ah1, ah2, ah3, bh[nt][0], bh[nt][1]);
                    mma_bf16(acc[mt][nt], ah0, ah1, ah2, ah3, bl[nt][0], bl[nt][1]);
                    mma_bf16(acc[mt][nt], al0, al1, al2, al3, bh[nt][0], bh[nt][1]);
                }
            }
        }
    }

    const float* vb = g_Y + (long)n * QKV * SS + 512;
    float* ob = g_O + (long)n * SS * EE;
#pragma unroll
    for (int mt = 0; mt < 4; mt++) {
        int r0 = i0 + wm * 64 + mt * 16 + gid;
#pragma unroll
        for (int nt = 0; nt < 8; nt++) {
            int col = ws * 64 + nt * 8 + tg * 2;
            float2 v0 = *(const float2*)(vb + (long)r0 * 768 + col);
            float2 v1 = *(const float2*)(vb + (long)(r0 + 8) * 768 + col);
            *(float2*)(ob + (long)r0 * 256 + col) =
                make_float2(acc[mt][nt][0] + v0.x, acc[mt][nt][1] + v0.y);
            *(float2*)(ob + (long)(r0 + 8) * 256 + col) =
                make_float2(acc[mt][nt][2] + v1.x, acc[mt][nt][3] + v1.y);
        }
    }
}

// ---------------- host ----------------
extern "C" void kernel_launch(void* const* d_in, const int* in_sizes, int n_in,
                              void* d_out, int out_size)
{
    const float* x     = (const float*)d_in[0];
    const float* w_qkv = (const float*)d_in[1];
    const float* b_qkv = (const float*)d_in[2];
    const float* w_out = (const float*)d_in[3];
    const float* b_out = (const float*)d_in[4];
    float* out = (float*)d_out;

    cudaFuncSetAttribute(k2inv_k, cudaFuncAttributeMaxDynamicSharedMemorySize,
                         K2INV_SMEM_FLOATS * (int)sizeof(float));
    cudaFuncSetAttribute(mma_gemm_k, cudaFuncAttributeMaxDynamicSharedMemorySize, MG_SMEM);
    cudaFuncSetAttribute(s1_mma_k, cudaFuncAttributeMaxDynamicSharedMemorySize, 2 * S1_STAGE);
    cudaFuncSetAttribute(s3_mma_k, cudaFuncAttributeMaxDynamicSharedMemorySize, 2 * S1_STAGE);
    cudaFuncSetAttribute(t3_mma_k, cudaFuncAttributeMaxDynamicSharedMemorySize, T3_SMEM);
    cudaFuncSetAttribute(out_mma_k, cudaFuncAttributeMaxDynamicSharedMemorySize, OUT_SMEM);

    void *yb, *ob;
    cudaGetSymbolAddress(&yb, g_Y);
    cudaGetSymbolAddress(&ob, g_O);
    void *wqh, *wql, *woh, *wol, *xh, *xl, *oh, *ol;
    cudaGetSymbolAddress(&wqh, g_wqh); cudaGetSymbolAddress(&wql, g_wql);
    cudaGetSymbolAddress(&woh, g_woh); cudaGetSymbolAddress(&wol, g_wol);
    cudaGetSymbolAddress(&xh, g_xh);   cudaGetSymbolAddress(&xl, g_xl);
    cudaGetSymbolAddress(&oh, g_oh);   cudaGetSymbolAddress(&ol, g_ol);

    // 0) operand conversion
    cvt_w_k<<<768, 256>>>(w_qkv, (__nv_bfloat16*)wqh, (__nv_bfloat16*)wql, QKV * 256);
    cvt_w_k<<<256, 256>>>(w_out, (__nv_bfloat16*)woh, (__nv_bfloat16*)wol, 256 * 256);
    tcvt_k<<<dim3(128, 8, NB), dim3(32, 8)>>>(x, (__nv_bfloat16*)xh, (__nv_bfloat16*)xl,
                                              (long)1048576);

    // 1) qkv projection
    mma_gemm_k<<<dim3(32, 6, NB), 256, MG_SMEM>>>(
        (const __nv_bfloat16*)wqh, (const __nv_bfloat16*)wql,
        (const __nv_bfloat16*)xh, (const __nv_bfloat16*)xl,
        (float*)yb, b_qkv, (long)SS * 256, (long)QKV * SS);

    // 2) fused q/k converts + landmarks + landmark converts; vT transpose convert
    qkland_k<<<dim3(NB, 64), 256>>>();
    vtcvt_k<<<dim3(128, 8, NB), dim3(32, 8)>>>();

    // 3) attention GEMMs
    s1_mma_k<<<dim3(32, NB), 256, 2 * S1_STAGE>>>();
    colstats_part_k<<<dim3(8, NB), 256>>>();
    colstats_comb_k<<<NB, 64>>>();
    s3_mma_k<<<dim3(32, NB), 256, 2 * S1_STAGE>>>();
    softmax_s3_k<<<dim3(16, NB), 256>>>();
    t3_mma_k<<<dim3(16, NB), 256, T3_SMEM>>>();
    t3_reduce_k<<<512, 256>>>();
    k2inv_k<<<NB, 1024, K2INV_SMEM_FLOATS * (int)sizeof(float)>>>();
    out_mma_k<<<dim3(32, NB), 256, OUT_SMEM>>>();

    // 4) output projection
    tcvt_k<<<dim3(128, 8, NB), dim3(32, 8)>>>((const float*)ob,
        (__nv_bfloat16*)oh, (__nv_bfloat16*)ol, (long)1048576);
    mma_gemm_k<<<dim3(32, 2, NB), 256, MG_SMEM>>>(
        (const __nv_bfloat16*)woh, (const __nv_bfloat16*)wol,
        (const __nv_bfloat16*)oh, (const __nv_bfloat16*)ol,
        out, b_out, (long)SS * 256, (long)256 * SS);
}

// round 14
// speedup vs baseline: 1.2104x; 1.0304x over previous
#include <cuda_runtime.h>
#include <cuda_bf16.h>
#include <cstdint>
#include <math.h>

#define NB   8
#define EE   256
#define LL   64
#define SS   4096
#define QKV  768

// ---------------- scratch ----------------
__device__ float g_Y[NB * QKV * SS];
__device__ float g_qland[NB * LL * EE];
__device__ float g_kland[NB * LL * EE];
__device__ float g_S1[NB * SS * LL];
__device__ float g_pmax[NB * 8 * LL];
__device__ float g_psum[NB * 8 * LL];
__device__ float g_m[NB * LL];
__device__ float g_sinv[NB * LL];
__device__ float g_S3[NB * LL * SS];
__device__ float g_T3p[NB * 16 * LL * EE];
__device__ float g_T3[NB * LL * EE];
__device__ float g_O[NB * SS * EE];

// split-bf16 operands
__device__ __nv_bfloat16 g_wqh[QKV * 256], g_wql[QKV * 256];
__device__ __nv_bfloat16 g_woh[256 * 256], g_wol[256 * 256];
__device__ __nv_bfloat16 g_xh[NB * SS * 256], g_xl[NB * SS * 256];
__device__ __nv_bfloat16 g_oh[NB * SS * 256], g_ol[NB * SS * 256];
__device__ __nv_bfloat16 g_qbh[NB * SS * 256], g_qbl[NB * SS * 256];
__device__ __nv_bfloat16 g_kbh[NB * SS * 256], g_kbl[NB * SS * 256];
__device__ __nv_bfloat16 g_vth[NB * 256 * SS], g_vtl[NB * 256 * SS];
__device__ __nv_bfloat16 g_qlbh[NB * LL * 256], g_qlbl[NB * LL * 256];
__device__ __nv_bfloat16 g_klbh[NB * LL * 256], g_klbl[NB * LL * 256];
__device__ __nv_bfloat16 g_M2h[NB * 256 * LL], g_M2l[NB * 256 * LL];

__device__ __forceinline__ uint32_t smem_u32(const void* p) {
    uint32_t a;
    asm("{ .reg .u64 t; cvta.to.shared.u64 t, %1; cvt.u32.u64 %0, t; }" : "=r"(a) : "l"(p));
    return a;
}
__device__ __forceinline__ void mma_bf16(float* d, uint32_t a0, uint32_t a1, uint32_t a2,
                                         uint32_t a3, uint32_t b0, uint32_t b1) {
    asm volatile(
        "mma.sync.aligned.m16n8k16.row.col.f32.bf16.bf16.f32 "
        "{%0,%1,%2,%3}, {%4,%5,%6,%7}, {%8,%9}, {%0,%1,%2,%3};"
        : "+f"(d[0]), "+f"(d[1]), "+f"(d[2]), "+f"(d[3])
        : "r"(a0), "r"(a1), "r"(a2), "r"(a3), "r"(b0), "r"(b1));
}
#define LDSM_X4(r0, r1, r2, r3, addr) \
    asm volatile("ldmatrix.sync.aligned.m8n8.x4.shared.b16 {%0,%1,%2,%3}, [%4];" \
        : "=r"(r0), "=r"(r1), "=r"(r2), "=r"(r3) : "r"(addr))
__device__ __forceinline__ uint32_t pack2(float a, float b) {
    __nv_bfloat162 h = __floats2bfloat162_rn(a, b);
    return *(uint32_t*)&h;
}
#define CPA16(d, s) asm volatile("cp.async.cg.shared.global [%0], [%1], 16;" :: "r"(d), "l"(s))
#define CPA_COMMIT() asm volatile("cp.async.commit_group;" ::: "memory")
#define CPA_WAIT0()  asm volatile("cp.async.wait_group 0;" ::: "memory")
#define CPA_WAIT1()  asm volatile("cp.async.wait_group 1;" ::: "memory")

// ================= big split-bf16 GEMM (R5 + ldmatrix fragment loads) =================
#define MG_STAGE 40960
#define MG_SMEM  (2 * MG_STAGE)
__global__ __launch_bounds__(256, 2) void mma_gemm_k(
    const __nv_bfloat16* __restrict__ Ah, const __nv_bfloat16* __restrict__ Al,
    const __nv_bfloat16* __restrict__ Bh, const __nv_bfloat16* __restrict__ Bl,
    float* __restrict__ C, const float* __restrict__ bias,
    long bStride, long cStride)
{
    extern __shared__ char smc[];
    const int tid = threadIdx.x;
    const int lane = tid & 31, wid = tid >> 5;
    const int wm = wid >> 2, ws = wid & 3;
    const int gid = lane >> 2, tg = lane & 3;
    const int n = blockIdx.z;
    const int m0 = blockIdx.y * 128, s0 = blockIdx.x * 128;

    const __nv_bfloat16* gsrc[4];
    gsrc[0] = Ah + (long)m0 * 256;
    gsrc[1] = Al + (long)m0 * 256;
    gsrc[2] = Bh + (long)n * bStride + (long)s0 * 256;
    gsrc[3] = Bl + (long)n * bStride + (long)s0 * 256;

    // ldmatrix lane-address components (constant per thread)
    const int a_lrow = lane & 15;                 // row within 16-row A tile
    const uint32_t a_kadj = ((lane >> 4) << 4);   // +16B for k8-15 matrices
    const int b_lrow = (lane & 7) + ((lane >> 4) << 3);  // row within 16-row B pair
    const uint32_t b_kadj = (((lane >> 3) & 1) << 4);

    float acc[4][4][4];
#pragma unroll
    for (int a = 0; a < 4; a++)
#pragma unroll
        for (int b = 0; b < 4; b++)
#pragma unroll
            for (int c = 0; c < 4; c++) acc[a][b][c] = 0.f;

    auto issue = [&](int c, int buf) {
#pragma unroll
        for (int it = 0; it < 8; it++) {
            int idx = tid + it * 256;
            int mat = idx >> 9, rr = (idx >> 2) & 127, seg = idx & 3;
            uint32_t d = smem_u32(smc + buf * MG_STAGE + mat * 10240 + rr * 80 + seg * 16);
            const __nv_bfloat16* s = gsrc[mat] + rr * 256 + c * 32 + seg * 8;
            CPA16(d, s);
        }
        CPA_COMMIT();
    };

    issue(0, 0);
    for (int c = 0; c < 8; c++) {
        if (c < 7) { issue(c + 1, (c + 1) & 1); CPA_WAIT1(); }
        else CPA_WAIT0();
        __syncthreads();
        const uint32_t stb = smem_u32(smc + (c & 1) * MG_STAGE);
#pragma unroll
        for (int ks = 0; ks < 2; ks++) {
            uint32_t bh[4][2], bl[4][2];
#pragma unroll
            for (int pr = 0; pr < 2; pr++) {
                int nrow = ws * 32 + pr * 16 + b_lrow;
                uint32_t boff = stb + 20480 + nrow * 80 + ks * 32 + b_kadj;
                LDSM_X4(bh[2 * pr][0], bh[2 * pr][1], bh[2 * pr + 1][0], bh[2 * pr + 1][1], boff);
                LDSM_X4(bl[2 * pr][0], bl[2 * pr][1], bl[2 * pr + 1][0], bl[2 * pr + 1][1],
                        boff + 10240);
            }
#pragma unroll
            for (int mt = 0; mt < 4; mt++) {
                int arow = wm * 64 + mt * 16 + a_lrow;
                uint32_t aoff = stb + arow * 80 + ks * 32 + a_kadj;
                uint32_t ah0, ah1, ah2, ah3, al0, al1, al2, al3;
                LDSM_X4(ah0, ah1, ah2, ah3, aoff);
                LDSM_X4(al0, al1, al2, al3, aoff + 10240);
#pragma unroll
                for (int nt = 0; nt < 4; nt++) {
                    mma_bf16(acc[mt][nt], ah0, ah1, ah2, ah3, bh[nt][0], bh[nt][1]);
                    mma_bf16(acc[mt][nt], ah0, ah1, ah2, ah3, bl[nt][0], bl[nt][1]);
                    mma_bf16(acc[mt][nt], al0, al1, al2, al3, bh[nt][0], bh[nt][1]);
                }
            }
        }
        __syncthreads();
    }

    float* Cn = C + (long)n * cStride;
#pragma unroll
    for (int mt = 0; mt < 4; mt++) {
        int r0 = m0 + wm * 64 + mt * 16 + gid;
        float b0v = bias[r0], b1v = bias[r0 + 8];
#pragma unroll
        for (int nt = 0; nt < 4; nt++) {
            int col = s0 + ws * 32 + nt * 8 + tg * 2;
            *(float2*)(Cn + (long)r0 * 4096 + col) =
                make_float2(acc[mt][nt][0] + b0v, acc[mt][nt][1] + b0v);
            *(float2*)(Cn + (long)(r0 + 8) * 4096 + col) =
                make_float2(acc[mt][nt][2] + b1v, acc[mt][nt][3] + b1v);
        }
    }
}

// ================= converts =================
__global__ void cvt_w_k(const float* __restrict__ src, __nv_bfloat16* __restrict__ hi,
                        __nv_bfloat16* __restrict__ lo, int nElem)
{
    int i = blockIdx.x * 256 + threadIdx.x;
    if (i < nElem) {
        float v = src[i];
        __nv_bfloat16 h = __float2bfloat16(v);
        hi[i] = h;
        lo[i] = __float2bfloat16(v - __bfloat162float(h));
    }
}

__global__ void tcvt_k(const float* __restrict__ src, __nv_bfloat16* __restrict__ hi,
                       __nv_bfloat16* __restrict__ lo, long srcBatchStride)
{
    __shared__ float t[32][33];
    int n = blockIdx.z;
    const float* S = src + (long)n * srcBatchStride;
    int s0 = blockIdx.x * 32, k0 = blockIdx.y * 32;
    int tx = threadIdx.x, ty = threadIdx.y;
#pragma unroll
    for (int i = 0; i < 32; i += 8) t[ty + i][tx] = S[(long)(k0 + ty + i) * 4096 + s0 + tx];
    __syncthreads();
    long base = (long)n * 1048576;
#pragma unroll
    for (int i = 0; i < 32; i += 8) {
        float v = t[tx][ty + i];
        __nv_bfloat16 h = __float2bfloat16(v);
        long o = base + (long)(s0 + ty + i) * 256 + k0 + tx;
        hi[o] = h;
        lo[o] = __float2bfloat16(v - __bfloat162float(h));
    }
}

// fused: q/k flat-view bf16 split converts + landmark means + landmark bf16 converts
__global__ __launch_bounds__(256) void qkland_k()
{
    int n = blockIdx.x, l = blockIdx.y, e = threadIdx.x;
    const float* base = g_Y + (long)n * 3145728 + (long)l * 64 * 768;
    float aq = 0.f, ak = 0.f;
    long obase = ((long)n * 4096 + l * 64) * 256 + e;
#pragma unroll 4
    for (int r = 0; r < 64; r++) {
        float q = base[r * 768 + e];
        float k = base[r * 768 + 256 + e];
        aq += q; ak += k;
        __nv_bfloat16 qh = __float2bfloat16(q);
        __nv_bfloat16 kh = __float2bfloat16(k);
        long o = obase + (long)r * 256;
        g_qbh[o] = qh; g_qbl[o] = __float2bfloat16(q - __bfloat162float(qh));
        g_kbh[o] = kh; g_kbl[o] = __float2bfloat16(k - __bfloat162float(kh));
    }
    int idx = (n * 64 + l) * 256 + e;
    float ql = aq * (1.f / 4096.f), kl = ak * (1.f / 4096.f);
    g_qland[idx] = ql; g_kland[idx] = kl;
    __nv_bfloat16 qlh = __float2bfloat16(ql), klh = __float2bfloat16(kl);
    g_qlbh[idx] = qlh; g_qlbl[idx] = __float2bfloat16(ql - __bfloat162float(qlh));
    g_klbh[idx] = klh; g_klbl[idx] = __float2bfloat16(kl - __bfloat162float(klh));
}

// vT transpose convert
__global__ void vtcvt_k()
{
    __shared__ float t[32][33];
    int n = blockIdx.z;
    int s0 = blockIdx.x * 32, e0 = blockIdx.y * 32;
    int tx = threadIdx.x, ty = threadIdx.y;
    const float* S = g_Y + (long)n * 3145728;
#pragma unroll
    for (int i = 0; i < 32; i += 8)
        t[ty + i][tx] = S[(long)(s0 + ty + i) * 768 + 512 + e0 + tx];
    __syncthreads();
    long base = (long)n * 1048576;
#pragma unroll
    for (int i = 0; i < 32; i += 8) {
        float v = t[tx][ty + i];
        __nv_bfloat16 h = __float2bfloat16(v);
        long o = base + (long)(e0 + ty + i) * 4096 + s0 + tx;
        g_vth[o] = h;
        g_vtl[o] = __float2bfloat16(v - __bfloat162float(h));
    }
}

// ================= S1 (verified R10) =================
#define S1_STAGE 30720
__global__ __launch_bounds__(256, 2) void s1_mma_k()
{
    extern __shared__ char smc[];
    int tid = threadIdx.x, lane = tid & 31, wid = tid >> 5;
    int wm = wid >> 1, ws = wid & 1, gid = lane >> 2, tg = lane & 3;
    int n = blockIdx.y, i0 = blockIdx.x * 128;
    const __nv_bfloat16* Ah = g_qbh + (long)n * 1048576 + (long)i0 * 256;
    const __nv_bfloat16* Al = g_qbl + (long)n * 1048576 + (long)i0 * 256;
    const __nv_bfloat16* Bh = g_klbh + n * 16384;
    const __nv_bfloat16* Bl = g_klbl + n * 16384;

    float acc[2][4][4];
#pragma unroll
    for (int a = 0; a < 2; a++)
#pragma unroll
        for (int b = 0; b < 4; b++)
#pragma unroll
            for (int c = 0; c < 4; c++) acc[a][b][c] = 0.f;

    auto issue = [&](int c, int buf) {
#pragma unroll
        for (int it = 0; it < 6; it++) {
            int idx = tid + it * 256;
            uint32_t d; const __nv_bfloat16* s;
            if (idx < 1024) {
                int half = idx >> 9, r = (idx >> 2) & 127, seg = idx & 3;
                d = smem_u32(smc + buf * S1_STAGE + half * 10240 + r * 80 + seg * 16);
                s = (half ? Al : Ah) + r * 256 + c * 32 + seg * 8;
            } else {
                int j = idx - 1024;
                int half = j >> 8, r = (j >> 2) & 63, seg = j & 3;
                d = smem_u32(smc + buf * S1_STAGE + 20480 + half * 5120 + r * 80 + seg * 16);
                s = (half ? Bl : Bh) + r * 256 + c * 32 + seg * 8;
            }
            CPA16(d, s);
        }
        CPA_COMMIT();
    };

    issue(0, 0);
    for (int c = 0; c < 8; c++) {
        if (c < 7) { issue(c + 1, (c + 1) & 1); CPA_WAIT1(); }
        else CPA_WAIT0();
        __syncthreads();
        const char* st = smc + (c & 1) * S1_STAGE;
#pragma unroll
        for (int ks = 0; ks < 2; ks++) {
            uint32_t bh[4][2], bl[4][2];
#pragma unroll
            for (int nt = 0; nt < 4; nt++) {
                int nrow = ws * 32 + nt * 8 + gid;
                const char* pb = st + 20480 + nrow * 80 + (ks * 16 + tg * 2) * 2;
                bh[nt][0] = *(const uint32_t*)pb;
                bh[nt][1] = *(const uint32_t*)(pb + 16);
                bl[nt][0] = *(const uint32_t*)(pb + 5120);
                bl[nt][1] = *(const uint32_t*)(pb + 5136);
            }
#pragma unroll
            for (int mt = 0; mt < 2; mt++) {
                int arow = wm * 32 + mt * 16 + gid;
                const char* pa = st + arow * 80 + (ks * 16 + tg * 2) * 2;
                uint32_t ah0 = *(const uint32_t*)pa;
                uint32_t ah1 = *(const uint32_t*)(pa + 640);
                uint32_t ah2 = *(const uint32_t*)(pa + 16);
                uint32_t ah3 = *(const uint32_t*)(pa + 656);
                uint32_t al0 = *(const uint32_t*)(pa + 10240);
                uint32_t al1 = *(const uint32_t*)(pa + 10880);
                uint32_t al2 = *(const uint32_t*)(pa + 10256);
                uint32_t al3 = *(const uint32_t*)(pa + 10896);
#pragma unroll
                for (int nt = 0; nt < 4; nt++) {
                    mma_bf16(acc[mt][nt], ah0, ah1, ah2, ah3, bh[nt][0], bh[nt][1]);
                    mma_bf16(acc[mt][nt], ah0, ah1, ah2, ah3, bl[nt][0], bl[nt][1]);
                    mma_bf16(acc[mt][nt], al0, al1, al2, al3, bh[nt][0], bh[nt][1]);
                }
            }
        }
        __syncthreads();
    }
#pragma unroll
    for (int mt = 0; mt < 2; mt++) {
        int r0 = i0 + wm * 32 + mt * 16 + gid;
#pragma unroll
        for (int nt = 0; nt < 4; nt++) {
            int col = ws * 32 + nt * 8 + tg * 2;
            float* dst = g_S1 + ((long)n * 4096 + r0) * 64 + col;
            *(float2*)dst = make_float2(acc[mt][nt][0], acc[mt][nt][1]);
            *(float2*)(dst + 512) = make_float2(acc[mt][nt][2], acc[mt][nt][3]);
        }
    }
}

// ================= S3 (verified R10) =================
__global__ __launch_bounds__(256, 2) void s3_mma_k()
{
    extern __shared__ char smc[];
    int tid = threadIdx.x, lane = tid & 31, wid = tid >> 5;
    int wm = wid >> 2, ws = wid & 3, gid = lane >> 2, tg = lane & 3;
    int n = blockIdx.y, s0 = blockIdx.x * 128;
    const __nv_bfloat16* Ah = g_qlbh + n * 16384;
    const __nv_bfloat16* Al = g_qlbl + n * 16384;
    const __nv_bfloat16* Bh = g_kbh + (long)n * 1048576 + (long)s0 * 256;
    const __nv_bfloat16* Bl = g_kbl + (long)n * 1048576 + (long)s0 * 256;

    float acc[2][4][4];
#pragma unroll
    for (int a = 0; a < 2; a++)
#pragma unroll
        for (int b = 0; b < 4; b++)
#pragma unroll
            for (int c = 0; c < 4; c++) acc[a][b][c] = 0.f;

    auto issue = [&](int c, int buf) {
#pragma unroll
        for (int it = 0; it < 6; it++) {
            int idx = tid + it * 256;
            uint32_t d; const __nv_bfloat16* s;
            if (idx < 512) {
                int half = idx >> 8, r = (idx >> 2) & 63, seg = idx & 3;
                d = smem_u32(smc + buf * S1_STAGE + half * 5120 + r * 80 + seg * 16);
                s = (half ? Al : Ah) + r * 256 + c * 32 + seg * 8;
            } else {
                int j = idx - 512;
                int half = j >> 9, r = (j >> 2) & 127, seg = j & 3;
                d = smem_u32(smc + buf * S1_STAGE + 10240 + half * 10240 + r * 80 + seg * 16);
                s = (half ? Bl : Bh) + r * 256 + c * 32 + seg * 8;
            }
            CPA16(d, s);
        }
        CPA_COMMIT();
    };

    issue(0, 0);
    for (int c = 0; c < 8; c++) {
        if (c < 7) { issue(c + 1, (c + 1) & 1); CPA_WAIT1(); }
        else CPA_WAIT0();
        __syncthreads();
        const char* st = smc + (c & 1) * S1_STAGE;
#pragma unroll
        for (int ks = 0; ks < 2; ks++) {
            uint32_t bh[4][2], bl[4][2];
#pragma unroll
            for (int nt = 0; nt < 4; nt++) {
                int nrow = ws * 32 + nt * 8 + gid;
                const char* pb = st + 10240 + nrow * 80 + (ks * 16 + tg * 2) * 2;
                bh[nt][0] = *(const uint32_t*)pb;
                bh[nt][1] = *(const uint32_t*)(pb + 16);
                bl[nt][0] = *(const uint32_t*)(pb + 10240);
                bl[nt][1] = *(const uint32_t*)(pb + 10256);
            }
#pragma unroll
            for (int mt = 0; mt < 2; mt++) {
                int arow = wm * 32 + mt * 16 + gid;
                const char* pa = st + arow * 80 + (ks * 16 + tg * 2) * 2;
                uint32_t ah0 = *(const uint32_t*)pa;
                uint32_t ah1 = *(const uint32_t*)(pa + 640);
                uint32_t ah2 = *(const uint32_t*)(pa + 16);
                uint32_t ah3 = *(const uint32_t*)(pa + 656);
                uint32_t al0 = *(const uint32_t*)(pa + 5120);
                uint32_t al1 = *(const uint32_t*)(pa + 5760);
                uint32_t al2 = *(const uint32_t*)(pa + 5136);
                uint32_t al3 = *(const uint32_t*)(pa + 5776);
#pragma unroll
                for (int nt = 0; nt < 4; nt++) {
                    mma_bf16(acc[mt][nt], ah0, ah1, ah2, ah3, bh[nt][0], bh[nt][1]);
                    mma_bf16(acc[mt][nt], ah0, ah1, ah2, ah3, bl[nt][0], bl[nt][1]);
                    mma_bf16(acc[mt][nt], al0, al1, al2, al3, bh[nt][0], bh[nt][1]);
                }
            }
        }
        __syncthreads();
    }
#pragma unroll
    for (int mt = 0; mt < 2; mt++) {
        int r0 = wm * 32 + mt * 16 + gid;
#pragma unroll
        for (int nt = 0; nt < 4; nt++) {
            int col = s0 + ws * 32 + nt * 8 + tg * 2;
            float* dst = g_S3 + (long)n * 262144 + (long)r0 * 4096 + col;
            *(float2*)dst = make_float2(acc[mt][nt][0], acc[mt][nt][1]);
            *(float2*)(dst + 8 * 4096) = make_float2(acc[mt][nt][2], acc[mt][nt][3]);
        }
    }
}

// ================= softmax helpers =================
__global__ void colstats_part_k()
{
    __shared__ float sm2[4][64];
    int stripe = blockIdx.x, n = blockIdx.y;
    int tid = threadIdx.x;
    int j = tid & 63, g = tid >> 6;
    const float* S = g_S1 + (long)n * SS * 64;
    float m = -1e30f;
    for (int i = stripe * 512 + g; i < stripe * 512 + 512; i += 4)
        m = fmaxf(m, S[(long)i * 64 + j]);
    sm2[g][j] = m;
    __syncthreads();
    float mm = fmaxf(fmaxf(sm2[0][j], sm2[1][j]), fmaxf(sm2[2][j], sm2[3][j]));
    float s = 0.f;
    for (int i = stripe * 512 + g; i < stripe * 512 + 512; i += 4)
        s += expf(S[(long)i * 64 + j] - mm);
    __syncthreads();
    sm2[g][j] = s;
    __syncthreads();
    if (g == 0) {
        float ss = sm2[0][j] + sm2[1][j] + sm2[2][j] + sm2[3][j];
        g_pmax[(n * 8 + stripe) * 64 + j] = mm;
        g_psum[(n * 8 + stripe) * 64 + j] = ss;
    }
}

__global__ void colstats_comb_k()
{
    int n = blockIdx.x, j = threadIdx.x;
    float m = -1e30f;
#pragma unroll
    for (int c = 0; c < 8; c++) m = fmaxf(m, g_pmax[(n * 8 + c) * 64 + j]);
    float s = 0.f;
#pragma unroll
    for (int c = 0; c < 8; c++)
        s += g_psum[(n * 8 + c) * 64 + j] * expf(g_pmax[(n * 8 + c) * 64 + j] - m);
    g_m[n * 64 + j] = m;
    g_sinv[n * 64 + j] = 1.f / s;
}

__global__ void softmax_s3_k()
{
    int n = blockIdx.y;
    int s = blockIdx.x * 256 + threadIdx.x;
    float* S = g_S3 + (long)n * LL * SS;
    float v[64];
    float m = -1e30f;
#pragma unroll
    for (int j = 0; j < 64; j++) { v[j] = S[(long)j * SS + s]; m = fmaxf(m, v[j]); }
    float sum = 0.f;
#pragma unroll
    for (int j = 0; j < 64; j++) { v[j] = expf(v[j] - m); sum += v[j]; }
    float r = 1.f / sum;
#pragma unroll
    for (int j = 0; j < 64; j++) S[(long)j * SS + s] = v[j] * r;
}

// ================= T3 (verified R10) =================
#define T3_SMEM 51200
__global__ __launch_bounds__(256, 2) void t3_mma_k()
{
    extern __shared__ char smc[];
    int tid = threadIdx.x, lane = tid & 31, wid = tid >> 5;
    int wm = wid >> 2, ws = wid & 3, gid = lane >> 2, tg = lane & 3;
    int n = blockIdx.y, s0 = blockIdx.x * 256;

    float acc[2][8][4];
#pragma unroll
    for (int a = 0; a < 2; a++)
#pragma unroll
        for (int b = 0; b < 8; b++)
#pragma unroll
            for (int c = 0; c < 4; c++) acc[a][b][c] = 0.f;

    for (int cc = 0; cc < 8; cc++) {
        {
            int j = tid >> 2, kq = (tid & 3) * 8;
            const float* s = g_S3 + (long)n * 262144 + (long)j * 4096 + s0 + cc * 32 + kq;
            float4 f0 = *(const float4*)s, f1 = *(const float4*)(s + 4);
            float v[8] = {f0.x, f0.y, f0.z, f0.w, f1.x, f1.y, f1.z, f1.w};
            uint32_t hi[4], lo[4];
#pragma unroll
            for (int p = 0; p < 4; p++) {
                __nv_bfloat16 h0 = __float2bfloat16(v[2 * p]);
                __nv_bfloat16 h1 = __float2bfloat16(v[2 * p + 1]);
                hi[p] = pack2(__bfloat162float(h0), __bfloat162float(h1));
                lo[p] = pack2(v[2 * p] - __bfloat162float(h0), v[2 * p + 1] - __bfloat162float(h1));
            }
            *(uint4*)(smc + 40960 + j * 80 + (kq >> 3) * 16) = *(uint4*)hi;
            *(uint4*)(smc + 46080 + j * 80 + (kq >> 3) * 16) = *(uint4*)lo;
        }
#pragma unroll
        for (int it = 0; it < 8; it++) {
            int idx = tid + it * 256;
            int half = idx >> 10, r = (idx >> 2) & 255, seg = idx & 3;
            uint32_t d = smem_u32(smc + half * 20480 + r * 80 + seg * 16);
            const __nv_bfloat16* s = (half ? g_vtl : g_vth) +
                (long)n * 1048576 + (long)r * 4096 + s0 + cc * 32 + seg * 8;
            CPA16(d, s);
        }
        CPA_COMMIT();
        CPA_WAIT0();
        __syncthreads();
#pragma unroll
        for (int ks = 0; ks < 2; ks++) {
            uint32_t bh[8][2], bl[8][2];
#pragma unroll
            for (int nt = 0; nt < 8; nt++) {
                int nrow = ws * 64 + nt * 8 + gid;
                const char* pb = smc + nrow * 80 + (ks * 16 + tg * 2) * 2;
                bh[nt][0] = *(const uint32_t*)pb;
                bh[nt][1] = *(const uint32_t*)(pb + 16);
                bl[nt][0] = *(const uint32_t*)(pb + 20480);
                bl[nt][1] = *(const uint32_t*)(pb + 20496);
            }
#pragma unroll
            for (int mt = 0; mt < 2; mt++) {
                int arow = wm * 32 + mt * 16 + gid;
                const char* pa = smc + 40960 + arow * 80 + (ks * 16 + tg * 2) * 2;
                uint32_t ah0 = *(const uint32_t*)pa;
                uint32_t ah1 = *(const uint32_t*)(pa + 640);
                uint32_t ah2 = *(const uint32_t*)(pa + 16);
                uint32_t ah3 = *(const uint32_t*)(pa + 656);
                uint32_t al0 = *(const uint32_t*)(pa + 5120);
                uint32_t al1 = *(const uint32_t*)(pa + 5760);
                uint32_t al2 = *(const uint32_t*)(pa + 5136);
                uint32_t al3 = *(const uint32_t*)(pa + 5776);
#pragma unroll
                for (int nt = 0; nt < 8; nt++) {
                    mma_bf16(acc[mt][nt], ah0, ah1, ah2, ah3, bh[nt][0], bh[nt][1]);
                    mma_bf16(acc[mt][nt], ah0, ah1, ah2, ah3, bl[nt][0], bl[nt][1]);
                    mma_bf16(acc[mt][nt], al0, al1, al2, al3, bh[nt][0], bh[nt][1]);
                }
            }
        }
        __syncthreads();
    }
    float* dst = g_T3p + (long)(n * 16 + blockIdx.x) * 16384;
#pragma unroll
    for (int mt = 0; mt < 2; mt++) {
        int r0 = wm * 32 + mt * 16 + gid;
#pragma unroll
        for (int nt = 0; nt < 8; nt++) {
            int col = ws * 64 + nt * 8 + tg * 2;
            *(float2*)(dst + r0 * 256 + col) = make_float2(acc[mt][nt][0], acc[mt][nt][1]);
            *(float2*)(dst + (r0 + 8) * 256 + col) = make_float2(acc[mt][nt][2], acc[mt][nt][3]);
        }
    }
}

__global__ void t3_reduce_k()
{
    int idx = blockIdx.x * 256 + threadIdx.x;
    int n = idx >> 14;
    int r = idx & 16383;
    const float* p = g_T3p + (long)n * 16 * 16384 + r;
    float s = 0.f;
#pragma unroll
    for (int c = 0; c < 16; c++) s += p[(long)c * 16384];
    g_T3[idx] = s;
}

// ================= k2inv v2 (verified R13) =================
#define KV_K2   0
#define KV_VV   4096
#define KV_BA   8192
#define KV_BB   12288
#define KV_BC   16384
#define KV_P    20480
#define KV_QLS  32768
#define KV_KTS  34816
#define KV_RED  36992
#define KV_T3S  8192
#define K2INV_SMEM_FLOATS 37184

__device__ __forceinline__ void mm64v2(float* D, const float* A, const float* B,
                                       float* P, int tid)
{
    int kg = tid >> 8;
    int t = tid & 255;
    int r0 = (t >> 4) * 4;
    int c0 = (t & 15) * 4;
    int kb = kg * 16;
    float acc[4][4];
#pragma unroll
    for (int a = 0; a < 4; a++)
#pragma unroll
        for (int b = 0; b < 4; b++) acc[a][b] = 0.f;

#pragma unroll
    for (int kk = 0; kk < 16; kk += 4) {
        float4 av[4];
#pragma unroll
        for (int rr = 0; rr < 4; rr++)
            av[rr] = *(const float4*)&A[(r0 + rr) * 64 + kb + kk];
#pragma unroll
        for (int kq = 0; kq < 4; kq++) {
            float4 b = *(const float4*)&B[(kb + kk + kq) * 64 + c0];
#pragma unroll
            for (int rr = 0; rr < 4; rr++) {
                float aw = reinterpret_cast<const float*>(&av[rr])[kq];
                acc[rr][0] += aw * b.x; acc[rr][1] += aw * b.y;
                acc[rr][2] += aw * b.z; acc[rr][3] += aw * b.w;
            }
        }
    }
    if (kg) {
        float* Pp = P + (kg - 1) * 4096;
#pragma unroll
        for (int rr = 0; rr < 4; rr++)
            *(float4*)&Pp[(r0 + rr) * 64 + c0] =
                make_float4(acc[rr][0], acc[rr][1], acc[rr][2], acc[rr][3]);
    }
    __syncthreads();
    if (kg == 0) {
#pragma unroll
        for (int rr = 0; rr < 4; rr++) {
            float4 s = make_float4(acc[rr][0], acc[rr][1], acc[rr][2], acc[rr][3]);
#pragma unroll
            for (int g = 0; g < 3; g++) {
                float4 p = *(const float4*)&P[g * 4096 + (r0 + rr) * 64 + c0];
                s.x += p.x; s.y += p.y; s.z += p.z; s.w += p.w;
            }
            *(float4*)&D[(r0 + rr) * 64 + c0] = s;
        }
    }
    __syncthreads();
}

__global__ __launch_bounds__(1024) void k2inv_k()
{
    extern __shared__ float sm[];
    float* K2 = sm + KV_K2;
    float* Vv = sm + KV_VV;
    float* BA = sm + KV_BA;
    float* BB = sm + KV_BB;
    float* BC = sm + KV_BC;
    float* P  = sm + KV_P;
    float* QLs = sm + KV_QLS;
    float* KTs = sm + KV_KTS;
    float* red = sm + KV_RED;

    int n = blockIdx.x;
    int tid = threadIdx.x;
    const float* ql = g_qland + n * 16384;
    const float* kl = g_kland + n * 16384;

    int st = tid & 255;
    int sr0 = (st >> 4) * 4;
    int sc0 = (st & 15) * 4;
    float accS[4][4];
#pragma unroll
    for (int a = 0; a < 4; a++)
#pragma unroll
        for (int b = 0; b < 4; b++) accS[a][b] = 0.f;

    for (int e0 = 0; e0 < 256; e0 += 32) {
#pragma unroll
        for (int p = 0; p < 2; p++) {
            int t2 = tid + p * 1024;
            int r = t2 >> 5, c = t2 & 31;
            QLs[r * 32 + c] = ql[r * 256 + e0 + c];
            KTs[c * 68 + r] = kl[r * 256 + e0 + c];
        }
        __syncthreads();
        if (tid < 256) {
#pragma unroll
            for (int kk = 0; kk < 32; kk += 4) {
                float4 av[4];
#pragma unroll
                for (int rr = 0; rr < 4; rr++)
                    av[rr] = *(const float4*)&QLs[(sr0 + rr) * 32 + kk];
#pragma unroll
                for (int kq = 0; kq < 4; kq++) {
                    float4 b = *(const float4*)&KTs[(kk + kq) * 68 + sc0];
#pragma unroll
                    for (int rr = 0; rr < 4; rr++) {
                        float aw = reinterpret_cast<const float*>(&av[rr])[kq];
                        accS[rr][0] += aw * b.x; accS[rr][1] += aw * b.y;
                        accS[rr][2] += aw * b.z; accS[rr][3] += aw * b.w;
                    }
                }
            }
        }
        __syncthreads();
    }
    if (tid < 256) {
#pragma unroll
        for (int rr = 0; rr < 4; rr++)
            *(float4*)&K2[(sr0 + rr) * 64 + sc0] =
                make_float4(accS[rr][0], accS[rr][1], accS[rr][2], accS[rr][3]);
    }
    __syncthreads();

    if (tid < 64) {
        int j = tid;
        float m = -1e30f;
        for (int i = 0; i < 64; i++) m = fmaxf(m, K2[i * 64 + j]);
        float s = 0.f;
        for (int i = 0; i < 64; i++) s += expf(K2[i * 64 + j] - m);
        red[j] = m; red[64 + j] = 1.f / s;
    }
    __syncthreads();
#pragma unroll
    for (int p = 0; p < 4; p++) {
        int t = tid + p * 1024;
        int j = t & 63;
        K2[t] = expf(K2[t] - red[j]) * red[64 + j];
    }
    __syncthreads();

    if (tid < 64) {
        int i = tid;
        float rs = 0.f, cs = 0.f;
        for (int j = 0; j < 64; j++) { rs += fabsf(K2[i * 64 + j]); cs += fabsf(K2[j * 64 + i]); }
        red[i] = rs; red[64 + i] = cs;
    }
    __syncthreads();
    if (tid == 0) {
        float vi = 0.f, v0 = 0.f;
        for (int t = 0; t < 64; t++) { vi = fmaxf(vi, red[t]); v0 = fmaxf(v0, red[64 + t]); }
        red[128] = 1.f / (v0 * vi);
    }
    __syncthreads();
    float isc = red[128];
#pragma unroll
    for (int p = 0; p < 4; p++) {
        int t = tid + p * 1024;
        int a = t >> 6, b = t & 63;
        Vv[t] = K2[b * 64 + a] * isc;
    }
    __syncthreads();

    for (int it = 0; it < 6; it++) {
        mm64v2(BA, K2, Vv, P, tid);
        mm64v2(BB, BA, BA, P, tid);
#pragma unroll
        for (int p = 0; p < 4; p++) {
            int t = tid + p * 1024;
            float d = ((t >> 6) == (t & 63)) ? 15.f : 0.f;
            BB[t] = d - 7.f * BA[t] + BB[t];
        }
        __syncthreads();
        mm64v2(BC, BA, BB, P, tid);
#pragma unroll
        for (int p = 0; p < 4; p++) {
            int t = tid + p * 1024;
            float d = ((t >> 6) == (t & 63)) ? 13.f : 0.f;
            BC[t] = d - BC[t];
        }
        __syncthreads();
        mm64v2(BB, Vv, BC, P, tid);
#pragma unroll
        for (int p = 0; p < 4; p++) {
            int t = tid + p * 1024;
            Vv[t] = 0.25f * BB[t];
        }
        __syncthreads();
    }

    float* T3s = sm + KV_T3S;
    for (int it = 0; it < 16; it++) {
        int idx = tid + it * 1024;
        T3s[idx] = g_T3[n * 16384 + idx];
    }
    __syncthreads();
    {
        int g = tid >> 8, t = tid & 255;
        int j0 = (t >> 4) * 4;
        int ec0 = g * 64 + (t & 15) * 4;
        float acc[4][4];
#pragma unroll
        for (int a = 0; a < 4; a++)
#pragma unroll
            for (int b = 0; b < 4; b++) acc[a][b] = 0.f;
#pragma unroll
        for (int kk = 0; kk < 64; kk += 4) {
            float4 av[4];
#pragma unroll
            for (int rr = 0; rr < 4; rr++)
                av[rr] = *(const float4*)&Vv[(j0 + rr) * 64 + kk];
#pragma unroll
            for (int kq = 0; kq < 4; kq++) {
                float4 b = *(const float4*)&T3s[(kk + kq) * 256 + ec0];
#pragma unroll
                for (int rr = 0; rr < 4; rr++) {
                    float aw = reinterpret_cast<const float*>(&av[rr])[kq];
                    acc[rr][0] += aw * b.x; acc[rr][1] += aw * b.y;
                    acc[rr][2] += aw * b.z; acc[rr][3] += aw * b.w;
                }
            }
        }
#pragma unroll
        for (int rr = 0; rr < 4; rr++) {
            float sv = g_sinv[n * 64 + j0 + rr];
#pragma unroll
            for (int cc = 0; cc < 4; cc++) {
                float a = acc[rr][cc] * sv;
                __nv_bfloat16 h = __float2bfloat16(a);
                long o = (long)n * 16384 + (long)(ec0 + cc) * 64 + j0 + rr;
                g_M2h[o] = h;
                g_M2l[o] = __float2bfloat16(a - __bfloat162float(h));
            }
        }
    }
}

// ================= out (verified R10) =================
#define OUT_SMEM 61696
__global__ __launch_bounds__(256, 1) void out_mma_k()
{
    extern __shared__ char smc[];
    float* ms = (float*)smc;
    int tid = threadIdx.x, lane = tid & 31, wid = tid >> 5;
    int wm = wid >> 2, ws = wid & 3, gid = lane >> 2, tg = lane & 3;
    int n = blockIdx.y, i0 = blockIdx.x * 128;

    if (tid < 64) ms[tid] = g_m[n * 64 + tid];
    __syncthreads();

    float acc[4][8][4];
#pragma unroll
    for (int a = 0; a < 4; a++)
#pragma unroll
        for (int b = 0; b < 8; b++)
#pragma unroll
            for (int c = 0; c < 4; c++) acc[a][b][c] = 0.f;

    for (int c = 0; c < 2; c++) {
        if (c) __syncthreads();
        {
            int row = tid >> 1, kq = (tid & 1) * 16;
            const float* Sr = g_S1 + ((long)n * 4096 + i0 + row) * 64 + c * 32 + kq;
            float v[16];
            *(float4*)&v[0]  = *(const float4*)Sr;
            *(float4*)&v[4]  = *(const float4*)(Sr + 4);
            *(float4*)&v[8]  = *(const float4*)(Sr + 8);
            *(float4*)&v[12] = *(const float4*)(Sr + 12);
            uint32_t hi[8], lo[8];
#pragma unroll
            for (int p = 0; p < 8; p++) {
                float e0 = expf(v[2 * p] - ms[c * 32 + kq + 2 * p]);
                float e1 = expf(v[2 * p + 1] - ms[c * 32 + kq + 2 * p + 1]);
                __nv_bfloat16 h0 = __float2bfloat16(e0), h1 = __float2bfloat16(e1);
                hi[p] = pack2(__bfloat162float(h0), __bfloat162float(h1));
                lo[p] = pack2(e0 - __bfloat162float(h0), e1 - __bfloat162float(h1));
            }
            char* pa = smc + 256 + row * 80 + (kq >> 3) * 16;
            *(uint4*)pa = *(uint4*)hi;
            *(uint4*)(pa + 16) = *(uint4*)&hi[4];
            char* pl = smc + 10496 + row * 80 + (kq >> 3) * 16;
            *(uint4*)pl = *(uint4*)lo;
            *(uint4*)(pl + 16) = *(uint4*)&lo[4];
        }
#pragma unroll
        for (int it = 0; it < 8; it++) {
            int idx = tid + it * 256;
            int half = idx >> 10, r = (idx >> 2) & 255, seg = idx & 3;
            uint32_t d = smem_u32(smc + 20736 + half * 20480 + r * 80 + seg * 16);
            const __nv_bfloat16* s = (half ? g_M2l : g_M2h) + n * 16384 + r * 64 + c * 32 + seg * 8;
            CPA16(d, s);
        }
        CPA_COMMIT();
        CPA_WAIT0();
        __syncthreads();
#pragma unroll
        for (int ks = 0; ks < 2; ks++) {
            uint32_t bh[8][2], bl[8][2];
#pragma unroll
            for (int nt = 0; nt < 8; nt++) {
                int nrow = ws * 64 + nt * 8 + gid;
                const char* pb = smc + 20736 + nrow * 80 + (ks * 16 + tg * 2) * 2;
                bh[nt][0] = *(const uint32_t*)pb;
                bh[nt][1] = *(const uint32_t*)(pb + 16);
                bl[nt][0] = *(const uint32_t*)(pb + 20480);
                bl[nt][1] = *(const uint32_t*)(pb + 20496);
            }
#pragma unroll
            for (int mt = 0; mt < 4; mt++) {
                int arow = wm * 64 + mt * 16 + gid;
                const char* pa = smc + 256 + arow * 80 + (ks * 16 + tg * 2) * 2;
                uint32_t ah0 = *(const uint32_t*)pa;
                uint32_t ah1 = *(const uint32_t*)(pa + 640);
                uint32_t ah2 = *(const uint32_t*)(pa + 16);
                uint32_t ah3 = *(const uint32_t*)(pa + 656);
                uint32_t al0 = *(const uint32_t*)(pa + 10240);
                uint32_t al1 = *(const uint32_t*)(pa + 10880);
                uint32_t al2 = *(const uint32_t*)(pa + 10256);
                uint32_t al3 = *(const uint32_t*)(pa + 10896);
#pragma unroll
                for (int nt = 0; nt < 8; nt++) {
                    mma_bf16(acc[mt][nt], ah0, ah1, ah2, ah3, bh[nt][0], bh[nt][1]);
                    mma_bf16(acc[mt][nt], ah0, ah1, ah2, ah3, bl[nt][0], bl[nt][1]);
                    mma_bf16(acc[mt][nt], al0, al1, al2, al3, bh[nt][0], bh[nt][1]);
                }
            }
        }
    }

    const float* vb = g_Y + (long)n * QKV * SS + 512;
    float* ob = g_O + (long)n * SS * EE;
#pragma unroll
    for (int mt = 0; mt < 4; mt++) {
        int r0 = i0 + wm * 64 + mt * 16 + gid;
#pragma unroll
        for (int nt = 0; nt < 8; nt++) {
            int col = ws * 64 + nt * 8 + tg * 2;
            float2 v0 = *(const float2*)(vb + (long)r0 * 768 + col);
            float2 v1 = *(const float2*)(vb + (long)(r0 + 8) * 768 + col);
            *(float2*)(ob + (long)r0 * 256 + col) =
                make_float2(acc[mt][nt][0] + v0.x, acc[mt][nt][1] + v0.y);
            *(float2*)(ob + (long)(r0 + 8) * 256 + col) =
                make_float2(acc[mt][nt][2] + v1.x, acc[mt][nt][3] + v1.y);
        }
    }
}

// ---------------- host ----------------
extern "C" void kernel_launch(void* const* d_in, const int* in_sizes, int n_in,
                              void* d_out, int out_size)
{
    const float* x     = (const float*)d_in[0];
    const float* w_qkv = (const float*)d_in[1];
    const float* b_qkv = (const float*)d_in[2];
    const float* w_out = (const float*)d_in[3];
    const float* b_out = (const float*)d_in[4];
    float* out = (float*)d_out;

    cudaFuncSetAttribute(k2inv_k, cudaFuncAttributeMaxDynamicSharedMemorySize,
                         K2INV_SMEM_FLOATS * (int)sizeof(float));
    cudaFuncSetAttribute(mma_gemm_k, cudaFuncAttributeMaxDynamicSharedMemorySize, MG_SMEM);
    cudaFuncSetAttribute(s1_mma_k, cudaFuncAttributeMaxDynamicSharedMemorySize, 2 * S1_STAGE);
    cudaFuncSetAttribute(s3_mma_k, cudaFuncAttributeMaxDynamicSharedMemorySize, 2 * S1_STAGE);
    cudaFuncSetAttribute(t3_mma_k, cudaFuncAttributeMaxDynamicSharedMemorySize, T3_SMEM);
    cudaFuncSetAttribute(out_mma_k, cudaFuncAttributeMaxDynamicSharedMemorySize, OUT_SMEM);

    void *yb, *ob;
    cudaGetSymbolAddress(&yb, g_Y);
    cudaGetSymbolAddress(&ob, g_O);
    void *wqh, *wql, *woh, *wol, *xh, *xl, *oh, *ol;
    cudaGetSymbolAddress(&wqh, g_wqh); cudaGetSymbolAddress(&wql, g_wql);
    cudaGetSymbolAddress(&woh, g_woh); cudaGetSymbolAddress(&wol, g_wol);
    cudaGetSymbolAddress(&xh, g_xh);   cudaGetSymbolAddress(&xl, g_xl);
    cudaGetSymbolAddress(&oh, g_oh);   cudaGetSymbolAddress(&ol, g_ol);

    // 0) operand conversion
    cvt_w_k<<<768, 256>>>(w_qkv, (__nv_bfloat16*)wqh, (__nv_bfloat16*)wql, QKV * 256);
    cvt_w_k<<<256, 256>>>(w_out, (__nv_bfloat16*)woh, (__nv_bfloat16*)wol, 256 * 256);
    tcvt_k<<<dim3(128, 8, NB), dim3(32, 8)>>>(x, (__nv_bfloat16*)xh, (__nv_bfloat16*)xl,
                                              (long)1048576);

    // 1) qkv projection
    mma_gemm_k<<<dim3(32, 6, NB), 256, MG_SMEM>>>(
        (const __nv_bfloat16*)wqh, (const __nv_bfloat16*)wql,
        (const __nv_bfloat16*)xh, (const __nv_bfloat16*)xl,
        (float*)yb, b_qkv, (long)SS * 256, (long)QKV * SS);

    // 2) fused q/k converts + landmarks; vT transpose convert
    qkland_k<<<dim3(NB, 64), 256>>>();
    vtcvt_k<<<dim3(128, 8, NB), dim3(32, 8)>>>();

    // 3) attention GEMMs
    s1_mma_k<<<dim3(32, NB), 256, 2 * S1_STAGE>>>();
    colstats_part_k<<<dim3(8, NB), 256>>>();
    colstats_comb_k<<<NB, 64>>>();
    s3_mma_k<<<dim3(32, NB), 256, 2 * S1_STAGE>>>();
    softmax_s3_k<<<dim3(16, NB), 256>>>();
    t3_mma_k<<<dim3(16, NB), 256, T3_SMEM>>>();
    t3_reduce_k<<<512, 256>>>();
    k2inv_k<<<NB, 1024, K2INV_SMEM_FLOATS * (int)sizeof(float)>>>();
    out_mma_k<<<dim3(32, NB), 256, OUT_SMEM>>>();

    // 4) output projection
    tcvt_k<<<dim3(128, 8, NB), dim3(32, 8)>>>((const float*)ob,
        (__nv_bfloat16*)oh, (__nv_bfloat16*)ol, (long)1048576);
    mma_gemm_k<<<dim3(32, 2, NB), 256, MG_SMEM>>>(
        (const __nv_bfloat16*)woh, (const __nv_bfloat16*)wol,
        (const __nv_bfloat16*)oh, (const __nv_bfloat16*)ol,
        out, b_out, (long)SS * 256, (long)256 * SS);
}